// round 5
// baseline (speedup 1.0000x reference)
#include <cuda_runtime.h>
#include <math.h>
#include <stdint.h>

// ---------------- problem constants ----------------
#define NN   200000
#define NI   64
#define NFD  128
#define NE   256
#define BB   16
#define KK   27
#define KDD  8
#define NDD  (NN / 8)        // 25000

#define STATS_BLOCKS 512
#define TILE_M 128
#define AW 36                 // padded smem row stride (floats); 144B, 16B-aligned
#define STAGES 3
#define STAGE_BYTES 18432     // 128 * AW * 4
#define CONV_SMEM (2 * STAGES * STAGE_BYTES)   // A + B, 3 stages = 110592 B

// ---------------- scratch (device globals; no allocation allowed) ----------------
__device__ float g_a  [(size_t)NN * NFD];     // tf32-rounded activations
__device__ float g_h  [(size_t)NN * NFD];     // conv1+film output (fp32)
__device__ float g_h2 [(size_t)NN * NFD];     // conv2+idconv output (tf32-rounded)
__device__ float g_xr [(size_t)NN * NI];      // tf32-rounded x (for idconv)
__device__ float g_part[STATS_BLOCKS * 2 * NFD];
__device__ float g_mv [2 * NFD];
__device__ float g_tp [BB * 2 * NFD];
__device__ float g_W1T[27 * 128 * 64];
__device__ float g_W2T[27 * 128 * 128];
__device__ float g_WiT[128 * 64];
__device__ float g_WdT[8 * 128 * 128];

// ---------------- helpers ----------------
__device__ __forceinline__ float silu_f(float x) { return x / (1.0f + expf(-x)); }

__device__ __forceinline__ float tf32r(float v) {
    unsigned u;
    asm("cvt.rna.tf32.f32 %0, %1;" : "=r"(u) : "f"(v));
    return __uint_as_float(u);
}

__device__ __forceinline__ uint32_t smem_u32(const void* p) {
    uint32_t a;
    asm("{ .reg .u64 t; cvta.to.shared.u64 t, %1; cvt.u32.u64 %0, t; }" : "=r"(a) : "l"(p));
    return a;
}

__device__ __forceinline__ void ldsm4(uint32_t* d, uint32_t addr) {
    asm volatile("ldmatrix.sync.aligned.m8n8.x4.shared.b16 {%0,%1,%2,%3}, [%4];"
                 : "=r"(d[0]), "=r"(d[1]), "=r"(d[2]), "=r"(d[3]) : "r"(addr));
}

__device__ __forceinline__ void mma_tf32(float* c, const uint32_t* a, const uint32_t* b) {
    asm volatile("mma.sync.aligned.m16n8k8.row.col.f32.tf32.tf32.f32 "
                 "{%0,%1,%2,%3}, {%4,%5,%6,%7}, {%8,%9}, {%0,%1,%2,%3};"
                 : "+f"(c[0]), "+f"(c[1]), "+f"(c[2]), "+f"(c[3])
                 : "r"(a[0]), "r"(a[1]), "r"(a[2]), "r"(a[3]), "r"(b[0]), "r"(b[1]));
}

__device__ __forceinline__ void cp16(uint32_t dst, const void* src, uint32_t srcsize) {
    asm volatile("cp.async.ca.shared.global [%0], [%1], 16, %2;"
                 :: "r"(dst), "l"(src), "r"(srcsize) : "memory");
}

// smem word offset for element (row r, half h of 16 floats)
__device__ __forceinline__ int sm_off(int r, int half) {
    return r * AW + ((half ^ (r & 1)) << 4);
}

// ---------------- BN statistics ----------------
template<int C>
__global__ void bn_stats_kernel(const float* __restrict__ X, int n, float* __restrict__ part) {
    constexpr int G = 256 / C;
    __shared__ float sh[512];
    int t = threadIdx.x;
    int c = t % C, g = t / C;
    float s = 0.f, s2 = 0.f;
    for (int r = blockIdx.x * G + g; r < n; r += gridDim.x * G) {
        float v = X[(size_t)r * C + c];
        s += v; s2 += v * v;
    }
    sh[t] = s; sh[256 + t] = s2;
    __syncthreads();
    if (t < C) {
        float a = 0.f, b = 0.f;
        #pragma unroll
        for (int gg = 0; gg < G; ++gg) { a += sh[gg * C + t]; b += sh[256 + gg * C + t]; }
        part[blockIdx.x * (2 * C) + t]     = a;
        part[blockIdx.x * (2 * C) + C + t] = b;
    }
}

template<int C>
__global__ void bn_finalize_kernel(const float* __restrict__ part, int nblocks, float invn,
                                   const float* __restrict__ g, const float* __restrict__ be,
                                   float* __restrict__ mv) {
    int c = threadIdx.x;
    if (c >= C) return;
    float s = 0.f, s2 = 0.f;
    for (int b = 0; b < nblocks; ++b) {
        s  += part[b * 2 * C + c];
        s2 += part[b * 2 * C + C + c];
    }
    float mean = s * invn;
    float var  = s2 * invn - mean * mean;
    float istd = rsqrtf(var + 1e-5f);
    float A = istd * g[c];
    mv[c]     = A;
    mv[C + c] = be[c] - mean * A;
}

// BN apply + SiLU, output rounded to tf32 (ready for mma A operand)
template<int C>
__global__ void bn_apply_silu_kernel(const float4* __restrict__ X, const float* __restrict__ mv,
                                     float4* __restrict__ Y, int n4) {
    int i = blockIdx.x * 256 + threadIdx.x;
    if (i >= n4) return;
    int f = (i & (C / 4 - 1)) * 4;
    float4 v = X[i];
    float4 o;
    o.x = tf32r(silu_f(fmaf(v.x, mv[f + 0], mv[C + f + 0])));
    o.y = tf32r(silu_f(fmaf(v.y, mv[f + 1], mv[C + f + 1])));
    o.z = tf32r(silu_f(fmaf(v.z, mv[f + 2], mv[C + f + 2])));
    o.w = tf32r(silu_f(fmaf(v.w, mv[f + 3], mv[C + f + 3])));
    Y[i] = o;
}

// plain tf32 rounding copy (for x -> xr)
__global__ void round_kernel(const float4* __restrict__ X, float4* __restrict__ Y, int n4) {
    int i = blockIdx.x * 256 + threadIdx.x;
    if (i >= n4) return;
    float4 v = X[i];
    float4 o;
    o.x = tf32r(v.x); o.y = tf32r(v.y); o.z = tf32r(v.z); o.w = tf32r(v.w);
    Y[i] = o;
}

// ---------------- time projection ----------------
__global__ void tproj_kernel(const float* __restrict__ T, const float* __restrict__ Wt,
                             const float* __restrict__ bt, float* __restrict__ tp) {
    __shared__ float ts[BB * NE];
    int t = threadIdx.x;
    for (int l = t; l < BB * NE; l += 256) ts[l] = silu_f(T[l]);
    __syncthreads();
    float acc[BB];
    #pragma unroll
    for (int b = 0; b < BB; ++b) acc[b] = 0.f;
    for (int e = 0; e < NE; ++e) {
        float w = Wt[e * 256 + t];
        #pragma unroll
        for (int b = 0; b < BB; ++b) acc[b] = fmaf(ts[b * NE + e], w, acc[b]);
    }
    float bias = bt[t];
    #pragma unroll
    for (int b = 0; b < BB; ++b) tp[b * 256 + t] = acc[b] + bias;
}

// ---------------- weight prep: transpose [K][CI][128] -> rna-tf32 [K][128][CI] ----------------
template<int CI>
__global__ void wprep_kernel(const float* __restrict__ W, float* __restrict__ WT) {
    __shared__ float tile[32][33];
    int k   = blockIdx.z;
    int ci0 = blockIdx.y * 32;
    int co0 = blockIdx.x * 32;
    int tx = threadIdx.x, ty = threadIdx.y;   // 32 x 8
    #pragma unroll
    for (int j = 0; j < 4; ++j) {
        int ci = ci0 + ty + j * 8;
        tile[ty + j * 8][tx] = W[((size_t)k * CI + ci) * 128 + co0 + tx];
    }
    __syncthreads();
    #pragma unroll
    for (int j = 0; j < 4; ++j) {
        int co = co0 + ty + j * 8;
        WT[((size_t)k * 128 + co) * CI + ci0 + tx] = tf32r(tile[tx][ty + j * 8]);
    }
}

// ---------------- mma.sync tf32 gather-GEMM (sparse conv), 3-stage cp.async ----------------
// MODE: 0 = plain, 1 = bias + FiLM fused, 2 = bias+bias2 + 2 idconv chunks, tf32-round out
struct Chunk {
    const float* a;   // activation source (tf32-rounded in gmem)
    int aCIN;
    const int* nb;    // neighbor row (nullptr = identity)
    const float* b;   // weight chunk base, already offset by cc
    int brs;
    int cc;
};

template<int CIN, int MODE>
__global__ __launch_bounds__(256, 2)
void conv_mma_kernel(const float* __restrict__ X, const int* __restrict__ nbr,
                     const float* __restrict__ BT, const float* __restrict__ bias,
                     const float* __restrict__ bias2, const float* __restrict__ tp,
                     const int* __restrict__ b_idx, const float* __restrict__ Xid,
                     const float* __restrict__ WiT,
                     float* __restrict__ out, int M, int K) {
    extern __shared__ float sm[];
    const uint32_t smA = smem_u32(sm);
    const uint32_t smB = smA + STAGES * STAGE_BYTES;

    constexpr int CPK = CIN / 32;
    const int MAIN  = K * CPK;
    const int TOTAL = MAIN + ((MODE == 2) ? 2 : 0);

    const int t = threadIdx.x;
    const int lane = t & 31, w = t >> 5;
    const int warpM = w >> 2, warpN = w & 3;
    const int rowBase = blockIdx.x * TILE_M;

    // loader roles
    const int lr_ = t >> 1;          // row 0..127
    const int lh  = t & 1;           // half (16 floats)
    const int myRow = rowBase + lr_;

    // ldmatrix address components
    const int g  = lane >> 3, lg = lane & 7;
    const int arow = warpM * 64 + lg + (g & 1) * 8;
    const int acg  = (g >> 1) * 4;
    const int ap   = arow & 1;
    const int brow = warpN * 32 + lg + (g >> 1) * 8;
    const int bcg  = (g & 1) * 4;
    const int bp   = brow & 1;

    float acc[4][4][4];
    #pragma unroll
    for (int i = 0; i < 4; ++i)
        #pragma unroll
        for (int j = 0; j < 4; ++j)
            #pragma unroll
            for (int q = 0; q < 4; ++q) acc[i][j][q] = 0.f;

    auto decode = [&](int c) -> Chunk {
        Chunk ch;
        if (MODE != 2 || c < MAIN) {
            int k  = c / CPK;
            int cc = (c - k * CPK) * 32;
            ch.a = X; ch.aCIN = CIN; ch.cc = cc;
            ch.nb = nbr + (size_t)k * M;
            ch.b = BT + ((size_t)k * 128) * CIN + cc; ch.brs = CIN;
        } else {
            int cc = (c - MAIN) * 32;
            ch.a = Xid; ch.aCIN = 64; ch.cc = cc;
            ch.nb = nullptr;
            ch.b = WiT + cc; ch.brs = 64;
        }
        return ch;
    };

    auto ldIdx = [&](int c) -> int {
        if (c >= TOTAL || myRow >= M) return -1;
        Chunk ch = decode(c);
        return ch.nb ? ch.nb[myRow] : myRow;
    };

    int idxCur = ldIdx(0);

    auto issue = [&](int c) {
        Chunk ch = decode(c);
        int idx = idxCur;
        idxCur = ldIdx(c + 1);                  // prefetch next chunk's index
        const int s = c % STAGES;
        // A gather: 4 x 16B, zfill when no neighbor
        uint32_t ad = smA + s * STAGE_BYTES + 4 * sm_off(lr_, lh);
        uint32_t sz = (idx >= 0) ? 16u : 0u;
        const char* ap_ = (const char*)(ch.a +
            (size_t)((idx >= 0) ? idx : 0) * ch.aCIN + ch.cc + lh * 16);
        #pragma unroll
        for (int j = 0; j < 4; ++j) cp16(ad + 16u * j, ap_ + 16 * j, sz);
        // B: 4 x 16B
        uint32_t bd = smB + s * STAGE_BYTES + 4 * sm_off(lr_, lh);
        const char* bp_ = (const char*)(ch.b + (size_t)lr_ * ch.brs + lh * 16);
        #pragma unroll
        for (int j = 0; j < 4; ++j) cp16(bd + 16u * j, bp_ + 16 * j, 16u);
        asm volatile("cp.async.commit_group;" ::: "memory");
    };

    // prologue: fill STAGES-1 stages
    issue(0);
    if (TOTAL > 1) issue(1);

    for (int c = 0; c < TOTAL; ++c) {
        asm volatile("cp.async.wait_group %0;" :: "n"(STAGES - 2) : "memory");
        __syncthreads();
        if (c + 2 < TOTAL) issue(c + 2);

        const int s = c % STAGES;
        const uint32_t abuf = smA + s * STAGE_BYTES;
        const uint32_t bbuf = smB + s * STAGE_BYTES;
        #pragma unroll
        for (int kt = 0; kt < 4; ++kt) {
            const int koA = 4 * ((((kt >> 1) ^ ap) << 4) + (kt & 1) * 8 + acg);
            const int koB = 4 * ((((kt >> 1) ^ bp) << 4) + (kt & 1) * 8 + bcg);
            uint32_t a[4][4];
            #pragma unroll
            for (int mt = 0; mt < 4; ++mt)
                ldsm4(a[mt], abuf + 4 * ((arow + mt * 16) * AW) + koA);
            uint32_t b[4][2];
            #pragma unroll
            for (int p = 0; p < 2; ++p) {
                uint32_t d[4];
                ldsm4(d, bbuf + 4 * ((brow + p * 16) * AW) + koB);
                b[2 * p][0] = d[0]; b[2 * p][1] = d[1];
                b[2 * p + 1][0] = d[2]; b[2 * p + 1][1] = d[3];
            }
            #pragma unroll
            for (int mt = 0; mt < 4; ++mt)
                #pragma unroll
                for (int nt = 0; nt < 4; ++nt)
                    mma_tf32(acc[mt][nt], a[mt], b[nt]);
        }
        __syncthreads();
    }

    // ---- epilogue ----
    #pragma unroll
    for (int mt = 0; mt < 4; ++mt) {
        int row0 = rowBase + warpM * 64 + mt * 16 + (lane >> 2);
        #pragma unroll
        for (int hr = 0; hr < 2; ++hr) {
            int row = row0 + 8 * hr;
            if (row >= M) continue;
            const float* tpr = (MODE == 1) ? (tp + b_idx[row] * 256) : nullptr;
            float* orow = out + (size_t)row * 128;
            #pragma unroll
            for (int nt = 0; nt < 4; ++nt) {
                int col = warpN * 32 + nt * 8 + 2 * (lane & 3);
                float v0 = acc[mt][nt][2 * hr + 0];
                float v1 = acc[mt][nt][2 * hr + 1];
                if (MODE == 1) {
                    v0 = (v0 + bias[col])     * (1.f + tpr[col])     + tpr[128 + col];
                    v1 = (v1 + bias[col + 1]) * (1.f + tpr[col + 1]) + tpr[129 + col];
                } else if (MODE == 2) {
                    v0 = tf32r(v0 + bias[col]     + bias2[col]);
                    v1 = tf32r(v1 + bias[col + 1] + bias2[col + 1]);
                }
                *(float2*)(orow + col) = make_float2(v0, v1);
            }
        }
    }
}

// ---------------- launch ----------------
extern "C" void kernel_launch(void* const* d_in, const int* in_sizes, int n_in,
                              void* d_out, int out_size) {
    const float* x     = (const float*)d_in[0];
    const float* t     = (const float*)d_in[1];
    const int*   b_idx = (const int*)  d_in[2];
    const int*   nbr   = (const int*)  d_in[3];
    const int*   nbrd  = (const int*)  d_in[4];
    const float* g1    = (const float*)d_in[5];
    const float* be1   = (const float*)d_in[6];
    const float* W1    = (const float*)d_in[7];
    const float* b1    = (const float*)d_in[8];
    const float* Wt    = (const float*)d_in[9];
    const float* bt    = (const float*)d_in[10];
    const float* g2    = (const float*)d_in[11];
    const float* be2   = (const float*)d_in[12];
    const float* W2    = (const float*)d_in[13];
    const float* b2    = (const float*)d_in[14];
    const float* Wid   = (const float*)d_in[15];
    const float* bid   = (const float*)d_in[16];
    const float* Wd    = (const float*)d_in[17];
    float* out = (float*)d_out;

    float *pa, *ph, *ph2, *pxr, *ppart, *pmv, *ptp, *pW1T, *pW2T, *pWiT, *pWdT;
    cudaGetSymbolAddress((void**)&pa,    g_a);
    cudaGetSymbolAddress((void**)&ph,    g_h);
    cudaGetSymbolAddress((void**)&ph2,   g_h2);
    cudaGetSymbolAddress((void**)&pxr,   g_xr);
    cudaGetSymbolAddress((void**)&ppart, g_part);
    cudaGetSymbolAddress((void**)&pmv,   g_mv);
    cudaGetSymbolAddress((void**)&ptp,   g_tp);
    cudaGetSymbolAddress((void**)&pW1T,  g_W1T);
    cudaGetSymbolAddress((void**)&pW2T,  g_W2T);
    cudaGetSymbolAddress((void**)&pWiT,  g_WiT);
    cudaGetSymbolAddress((void**)&pWdT,  g_WdT);

    cudaFuncSetAttribute(conv_mma_kernel<64, 1>,  cudaFuncAttributeMaxDynamicSharedMemorySize, CONV_SMEM);
    cudaFuncSetAttribute(conv_mma_kernel<128, 2>, cudaFuncAttributeMaxDynamicSharedMemorySize, CONV_SMEM);
    cudaFuncSetAttribute(conv_mma_kernel<128, 0>, cudaFuncAttributeMaxDynamicSharedMemorySize, CONV_SMEM);

    const float invn = 1.0f / (float)NN;
    const int convGrid = (NN + TILE_M - 1) / TILE_M;   // 1563
    const int downGrid = (NDD + TILE_M - 1) / TILE_M;  // 196
    dim3 tb(32, 8);

    // ---- weight prep (transpose + rna tf32) ----
    wprep_kernel<64> <<<dim3(4, 2, 27), tb>>>(W1,  pW1T);
    wprep_kernel<128><<<dim3(4, 4, 27), tb>>>(W2,  pW2T);
    wprep_kernel<64> <<<dim3(4, 2, 1),  tb>>>(Wid, pWiT);
    wprep_kernel<128><<<dim3(4, 4, 8),  tb>>>(Wd,  pWdT);

    // ---- round x for idconv ----
    {
        int n4 = NN * NI / 4;
        round_kernel<<<(n4 + 255) / 256, 256>>>((const float4*)x, (float4*)pxr, n4);
    }
    // ---- BN1(x) + SiLU -> a (tf32) ----
    bn_stats_kernel<NI><<<STATS_BLOCKS, 256>>>(x, NN, ppart);
    bn_finalize_kernel<NI><<<1, NI>>>(ppart, STATS_BLOCKS, invn, g1, be1, pmv);
    {
        int n4 = NN * NI / 4;
        bn_apply_silu_kernel<NI><<<(n4 + 255) / 256, 256>>>((const float4*)x, pmv, (float4*)pa, n4);
    }
    // ---- time projection ----
    tproj_kernel<<<1, 256>>>(t, Wt, bt, ptp);
    // ---- conv1 (+bias +FiLM fused) -> h (fp32) ----
    conv_mma_kernel<64, 1><<<convGrid, 256, CONV_SMEM>>>(
        pa, nbr, pW1T, b1, nullptr, ptp, b_idx, nullptr, nullptr, ph, NN, KK);
    // ---- BN2(h) + SiLU -> a (tf32) ----
    bn_stats_kernel<NFD><<<STATS_BLOCKS, 256>>>(ph, NN, ppart);
    bn_finalize_kernel<NFD><<<1, NFD>>>(ppart, STATS_BLOCKS, invn, g2, be2, pmv);
    {
        int n4 = NN * NFD / 4;
        bn_apply_silu_kernel<NFD><<<(n4 + 255) / 256, 256>>>((const float4*)ph, pmv, (float4*)pa, n4);
    }
    // ---- conv2 + fused idconv (+b2+bid) -> h2 (tf32) ----
    conv_mma_kernel<128, 2><<<convGrid, 256, CONV_SMEM>>>(
        pa, nbr, pW2T, b2, bid, nullptr, nullptr, pxr, pWiT, ph2, NN, KK);
    // ---- strided down conv -> out (fp32) ----
    conv_mma_kernel<128, 0><<<downGrid, 256, CONV_SMEM>>>(
        ph2, nbrd, pWdT, nullptr, nullptr, nullptr, nullptr, nullptr, nullptr, out, NDD, KDD);

    (void)in_sizes; (void)n_in; (void)out_size;
}

// round 6
// speedup vs baseline: 1.1588x; 1.1588x over previous
#include <cuda_runtime.h>
#include <math.h>
#include <stdint.h>

// ---------------- problem constants ----------------
#define NN   200000
#define NI   64
#define NFD  128
#define NE   256
#define BB   16
#define KK   27
#define KDD  8
#define NDD  (NN / 8)        // 25000

#define STATS_BLOCKS 512
#define TILE_M 128
#define AW 36                 // padded smem row stride (floats)
#define CONV_SMEM (2 * (128 * AW) * 4 * 2)   // A(2 bufs) + B(2 bufs) = 73728 B

// ---------------- scratch (device globals; no allocation allowed) ----------------
__device__ float g_a  [(size_t)NN * NFD];
__device__ float g_h  [(size_t)NN * NFD];
__device__ float g_h2 [(size_t)NN * NFD];
__device__ float g_part[STATS_BLOCKS * 2 * NFD];
__device__ float g_mv [2 * NFD];
__device__ float g_tp [BB * 2 * NFD];
__device__ float g_W1T[27 * 128 * 64];
__device__ float g_W2T[27 * 128 * 128];
__device__ float g_WiT[128 * 64];
__device__ float g_WdT[8 * 128 * 128];

// ---------------- helpers ----------------
__device__ __forceinline__ float silu_f(float x) { return x / (1.0f + expf(-x)); }

__device__ __forceinline__ float tf32r(float v) {
    unsigned u;
    asm("cvt.rna.tf32.f32 %0, %1;" : "=r"(u) : "f"(v));
    return __uint_as_float(u);
}

__device__ __forceinline__ uint32_t smem_u32(const void* p) {
    uint32_t a;
    asm("{ .reg .u64 t; cvta.to.shared.u64 t, %1; cvt.u32.u64 %0, t; }" : "=r"(a) : "l"(p));
    return a;
}

__device__ __forceinline__ void ldsm4(uint32_t* d, uint32_t addr) {
    asm volatile("ldmatrix.sync.aligned.m8n8.x4.shared.b16 {%0,%1,%2,%3}, [%4];"
                 : "=r"(d[0]), "=r"(d[1]), "=r"(d[2]), "=r"(d[3]) : "r"(addr));
}

__device__ __forceinline__ void mma_tf32(float* c, const uint32_t* a, const uint32_t* b) {
    asm volatile("mma.sync.aligned.m16n8k8.row.col.f32.tf32.tf32.f32 "
                 "{%0,%1,%2,%3}, {%4,%5,%6,%7}, {%8,%9}, {%0,%1,%2,%3};"
                 : "+f"(c[0]), "+f"(c[1]), "+f"(c[2]), "+f"(c[3])
                 : "r"(a[0]), "r"(a[1]), "r"(a[2]), "r"(a[3]), "r"(b[0]), "r"(b[1]));
}

// smem word offset for element (row r, half h of 16 floats)
__device__ __forceinline__ int sm_off(int r, int half) {
    return r * AW + ((half ^ (r & 1)) << 4);
}

// ---------------- fused weight prep: transpose [K][CI][128] -> rna-tf32 [K][128][CI] ----------------
__global__ void wprep_all_kernel(const float* __restrict__ W1, const float* __restrict__ W2,
                                 const float* __restrict__ Wid, const float* __restrict__ Wd,
                                 float* __restrict__ W1T, float* __restrict__ W2T,
                                 float* __restrict__ WiT, float* __restrict__ WdT) {
    __shared__ float tile[32][33];
    int b = blockIdx.x;
    const float* W; float* WT; int CI, k, cit, cot;
    if (b < 216)      { int r = b;       W = W1;  WT = W1T; CI = 64;  k = r / 8;  int q = r % 8;  cit = q / 4; cot = q % 4; }
    else if (b < 648) { int r = b - 216; W = W2;  WT = W2T; CI = 128; k = r / 16; int q = r % 16; cit = q / 4; cot = q % 4; }
    else if (b < 656) { int r = b - 648; W = Wid; WT = WiT; CI = 64;  k = 0;      cit = r / 4;    cot = r % 4; }
    else              { int r = b - 656; W = Wd;  WT = WdT; CI = 128; k = r / 16; int q = r % 16; cit = q / 4; cot = q % 4; }
    int ci0 = cit * 32, co0 = cot * 32;
    int tx = threadIdx.x, ty = threadIdx.y;   // 32 x 8
    #pragma unroll
    for (int j = 0; j < 4; ++j) {
        int ci = ci0 + ty + j * 8;
        tile[ty + j * 8][tx] = W[((size_t)k * CI + ci) * 128 + co0 + tx];
    }
    __syncthreads();
    #pragma unroll
    for (int j = 0; j < 4; ++j) {
        int co = co0 + ty + j * 8;
        WT[((size_t)k * 128 + co) * CI + ci0 + tx] = tf32r(tile[tx][ty + j * 8]);
    }
}

// ---------------- time projection ----------------
__global__ void tproj_kernel(const float* __restrict__ T, const float* __restrict__ Wt,
                             const float* __restrict__ bt, float* __restrict__ tp) {
    __shared__ float ts[BB * NE];
    int t = threadIdx.x;
    for (int l = t; l < BB * NE; l += 256) ts[l] = silu_f(T[l]);
    __syncthreads();
    float acc[BB];
    #pragma unroll
    for (int b = 0; b < BB; ++b) acc[b] = 0.f;
    for (int e = 0; e < NE; ++e) {
        float w = Wt[e * 256 + t];
        #pragma unroll
        for (int b = 0; b < BB; ++b) acc[b] = fmaf(ts[b * NE + e], w, acc[b]);
    }
    float bias = bt[t];
    #pragma unroll
    for (int b = 0; b < BB; ++b) tp[b * 256 + t] = acc[b] + bias;
}

// ---------------- BN statistics ----------------
template<int C>
__global__ void bn_stats_kernel(const float* __restrict__ X, int n, float* __restrict__ part) {
    constexpr int G = 256 / C;
    __shared__ float sh[512];
    int t = threadIdx.x;
    int c = t % C, g = t / C;
    float s = 0.f, s2 = 0.f;
    for (int r = blockIdx.x * G + g; r < n; r += gridDim.x * G) {
        float v = X[(size_t)r * C + c];
        s += v; s2 += v * v;
    }
    sh[t] = s; sh[256 + t] = s2;
    __syncthreads();
    if (t < C) {
        float a = 0.f, b = 0.f;
        #pragma unroll
        for (int gg = 0; gg < G; ++gg) { a += sh[gg * C + t]; b += sh[256 + gg * C + t]; }
        part[blockIdx.x * (2 * C) + t]     = a;
        part[blockIdx.x * (2 * C) + C + t] = b;
    }
}

template<int C>
__global__ void bn_finalize_kernel(const float* __restrict__ part, int nblocks, float invn,
                                   const float* __restrict__ g, const float* __restrict__ be,
                                   float* __restrict__ mv) {
    int c = threadIdx.x;
    if (c >= C) return;
    float s = 0.f, s2 = 0.f;
    for (int b = 0; b < nblocks; ++b) {
        s  += part[b * 2 * C + c];
        s2 += part[b * 2 * C + C + c];
    }
    float mean = s * invn;
    float var  = s2 * invn - mean * mean;
    float istd = rsqrtf(var + 1e-5f);
    float A = istd * g[c];
    mv[c]     = A;
    mv[C + c] = be[c] - mean * A;
}

template<int C>
__global__ void bn_apply_silu_kernel(const float4* __restrict__ X, const float* __restrict__ mv,
                                     float4* __restrict__ Y, int n4) {
    int i = blockIdx.x * 256 + threadIdx.x;
    if (i >= n4) return;
    int f = (i & (C / 4 - 1)) * 4;
    float4 v = X[i];
    float4 o;
    o.x = silu_f(fmaf(v.x, mv[f + 0], mv[C + f + 0]));
    o.y = silu_f(fmaf(v.y, mv[f + 1], mv[C + f + 1]));
    o.z = silu_f(fmaf(v.z, mv[f + 2], mv[C + f + 2]));
    o.w = silu_f(fmaf(v.w, mv[f + 3], mv[C + f + 3]));
    Y[i] = o;
}

// ---------------- mma.sync tf32 gather-GEMM (sparse conv) ----------------
// MODE: 0 = plain, 1 = bias + FiLM fused, 2 = bias+bias2 with 2 extra idconv chunks
struct Chunk {
    const float* a;   // activation source
    int aCIN;         // its row stride
    const int* nb;    // neighbor row (nullptr = identity)
    const float* b;   // weight chunk base (row stride brs), already offset by cc
    int brs;
    int cc;           // channel offset into activation row
};

template<int CIN, int MODE>
__global__ __launch_bounds__(256, 2)
void conv_mma_kernel(const float* __restrict__ X, const int* __restrict__ nbr,
                     const float* __restrict__ BT, const float* __restrict__ bias,
                     const float* __restrict__ bias2, const float* __restrict__ tp,
                     const int* __restrict__ b_idx, const float* __restrict__ Xid,
                     const float* __restrict__ WiT,
                     float* __restrict__ out, int M, int K) {
    extern __shared__ float sm[];
    const uint32_t smA = smem_u32(sm);            // A: 2 x 18432 B
    const uint32_t smB = smA + 36864;             // B: 2 x 18432 B

    constexpr int CPK = CIN / 32;
    const int MAIN  = K * CPK;
    const int TOTAL = MAIN + ((MODE == 2) ? 2 : 0);

    const int t = threadIdx.x;
    const int lane = t & 31, w = t >> 5;
    const int warpM = w >> 2, warpN = w & 3;
    const int rowBase = blockIdx.x * TILE_M;

    // loader roles
    const int lr_ = t >> 1;          // row 0..127
    const int lh  = t & 1;           // half (16 floats)

    // ldmatrix address components
    const int g  = lane >> 3, lg = lane & 7;
    const int arow = warpM * 64 + lg + (g & 1) * 8;       // + mt*16
    const int acg  = (g >> 1) * 4;                        // A col within k8
    const int ap   = arow & 1;
    const int brow = warpN * 32 + lg + (g >> 1) * 8;      // + p*16
    const int bcg  = (g & 1) * 4;
    const int bp   = brow & 1;

    float acc[4][4][4];
    #pragma unroll
    for (int i = 0; i < 4; ++i)
        #pragma unroll
        for (int j = 0; j < 4; ++j)
            #pragma unroll
            for (int q = 0; q < 4; ++q) acc[i][j][q] = 0.f;

    auto decode = [&](int c) -> Chunk {
        Chunk ch;
        if (MODE != 2 || c < MAIN) {
            int k  = c / CPK;
            int cc = (c - k * CPK) * 32;
            ch.a = X; ch.aCIN = CIN; ch.cc = cc;
            ch.nb = nbr + (size_t)k * M;
            ch.b = BT + ((size_t)k * 128) * CIN + cc; ch.brs = CIN;
        } else {
            int cc = (c - MAIN) * 32;
            ch.a = Xid; ch.aCIN = 64; ch.cc = cc;
            ch.nb = nullptr;
            ch.b = WiT + cc; ch.brs = 64;
        }
        return ch;
    };

    float4 va[4];
    auto ldA = [&](const Chunk& ch) {
        int row = rowBase + lr_;
        int idx = -1;
        if (row < M) idx = ch.nb ? ch.nb[row] : row;
        if (idx >= 0) {
            const float4* p = (const float4*)(ch.a + (size_t)idx * ch.aCIN + ch.cc + lh * 16);
            va[0] = p[0]; va[1] = p[1]; va[2] = p[2]; va[3] = p[3];
        } else {
            va[0] = va[1] = va[2] = va[3] = make_float4(0.f, 0.f, 0.f, 0.f);
        }
    };
    auto stsA = [&](int bu) {
        float* dst = sm + bu * 4608 + sm_off(lr_, lh);
        #pragma unroll
        for (int j = 0; j < 4; ++j) {
            float4 o;
            o.x = tf32r(va[j].x); o.y = tf32r(va[j].y);
            o.z = tf32r(va[j].z); o.w = tf32r(va[j].w);
            ((float4*)dst)[j] = o;
        }
    };
    auto cpB = [&](const Chunk& ch, int bu) {
        uint32_t bd = smB + bu * 18432 + 4 * sm_off(lr_, lh);
        const char* gp = (const char*)(ch.b + (size_t)lr_ * ch.brs + lh * 16);
        #pragma unroll
        for (int j = 0; j < 4; ++j)
            asm volatile("cp.async.ca.shared.global [%0], [%1], 16;"
                         :: "r"(bd + 16u * j), "l"(gp + 16 * j) : "memory");
        asm volatile("cp.async.commit_group;" ::: "memory");
    };

    // prologue
    {
        Chunk c0 = decode(0);
        ldA(c0);
        cpB(c0, 0);
    }

    for (int c = 0; c < TOTAL; ++c) {
        const int bu = c & 1;
        stsA(bu);
        asm volatile("cp.async.wait_group 0;" ::: "memory");
        __syncthreads();
        if (c + 1 < TOTAL) {
            Chunk cn = decode(c + 1);
            ldA(cn);
            cpB(cn, bu ^ 1);
        }
        // ---- compute chunk c ----
        const uint32_t abuf = smA + bu * 18432;
        const uint32_t bbuf = smB + bu * 18432;
        #pragma unroll
        for (int kt = 0; kt < 4; ++kt) {
            const int koA = 4 * ((((kt >> 1) ^ ap) << 4) + (kt & 1) * 8 + acg);
            const int koB = 4 * ((((kt >> 1) ^ bp) << 4) + (kt & 1) * 8 + bcg);
            uint32_t a[4][4];
            #pragma unroll
            for (int mt = 0; mt < 4; ++mt)
                ldsm4(a[mt], abuf + 4 * ((arow + mt * 16) * AW) + koA);
            uint32_t b[4][2];
            #pragma unroll
            for (int p = 0; p < 2; ++p) {
                uint32_t d[4];
                ldsm4(d, bbuf + 4 * ((brow + p * 16) * AW) + koB);
                b[2 * p][0] = d[0]; b[2 * p][1] = d[1];
                b[2 * p + 1][0] = d[2]; b[2 * p + 1][1] = d[3];
            }
            #pragma unroll
            for (int mt = 0; mt < 4; ++mt)
                #pragma unroll
                for (int nt = 0; nt < 4; ++nt)
                    mma_tf32(acc[mt][nt], a[mt], b[nt]);
        }
    }

    // ---- epilogue ----
    #pragma unroll
    for (int mt = 0; mt < 4; ++mt) {
        int row0 = rowBase + warpM * 64 + mt * 16 + (lane >> 2);
        #pragma unroll
        for (int hr = 0; hr < 2; ++hr) {
            int row = row0 + 8 * hr;
            if (row >= M) continue;
            const float* tpr = (MODE == 1) ? (tp + b_idx[row] * 256) : nullptr;
            float* orow = out + (size_t)row * 128;
            #pragma unroll
            for (int nt = 0; nt < 4; ++nt) {
                int col = warpN * 32 + nt * 8 + 2 * (lane & 3);
                float v0 = acc[mt][nt][2 * hr + 0];
                float v1 = acc[mt][nt][2 * hr + 1];
                if (MODE == 1) {
                    v0 = (v0 + bias[col])     * (1.f + tpr[col])     + tpr[128 + col];
                    v1 = (v1 + bias[col + 1]) * (1.f + tpr[col + 1]) + tpr[129 + col];
                } else if (MODE == 2) {
                    v0 += bias[col] + bias2[col];
                    v1 += bias[col + 1] + bias2[col + 1];
                }
                *(float2*)(orow + col) = make_float2(v0, v1);
            }
        }
    }
}

// ---------------- launch ----------------
extern "C" void kernel_launch(void* const* d_in, const int* in_sizes, int n_in,
                              void* d_out, int out_size) {
    const float* x     = (const float*)d_in[0];
    const float* t     = (const float*)d_in[1];
    const int*   b_idx = (const int*)  d_in[2];
    const int*   nbr   = (const int*)  d_in[3];
    const int*   nbrd  = (const int*)  d_in[4];
    const float* g1    = (const float*)d_in[5];
    const float* be1   = (const float*)d_in[6];
    const float* W1    = (const float*)d_in[7];
    const float* b1    = (const float*)d_in[8];
    const float* Wt    = (const float*)d_in[9];
    const float* bt    = (const float*)d_in[10];
    const float* g2    = (const float*)d_in[11];
    const float* be2   = (const float*)d_in[12];
    const float* W2    = (const float*)d_in[13];
    const float* b2    = (const float*)d_in[14];
    const float* Wid   = (const float*)d_in[15];
    const float* bid   = (const float*)d_in[16];
    const float* Wd    = (const float*)d_in[17];
    float* out = (float*)d_out;

    float *pa, *ph, *ph2, *ppart, *pmv, *ptp, *pW1T, *pW2T, *pWiT, *pWdT;
    cudaGetSymbolAddress((void**)&pa,    g_a);
    cudaGetSymbolAddress((void**)&ph,    g_h);
    cudaGetSymbolAddress((void**)&ph2,   g_h2);
    cudaGetSymbolAddress((void**)&ppart, g_part);
    cudaGetSymbolAddress((void**)&pmv,   g_mv);
    cudaGetSymbolAddress((void**)&ptp,   g_tp);
    cudaGetSymbolAddress((void**)&pW1T,  g_W1T);
    cudaGetSymbolAddress((void**)&pW2T,  g_W2T);
    cudaGetSymbolAddress((void**)&pWiT,  g_WiT);
    cudaGetSymbolAddress((void**)&pWdT,  g_WdT);

    cudaFuncSetAttribute(conv_mma_kernel<64, 1>,  cudaFuncAttributeMaxDynamicSharedMemorySize, CONV_SMEM);
    cudaFuncSetAttribute(conv_mma_kernel<128, 2>, cudaFuncAttributeMaxDynamicSharedMemorySize, CONV_SMEM);
    cudaFuncSetAttribute(conv_mma_kernel<128, 0>, cudaFuncAttributeMaxDynamicSharedMemorySize, CONV_SMEM);

    const float invn = 1.0f / (float)NN;
    const int convGrid = (NN + TILE_M - 1) / TILE_M;   // 1563
    const int downGrid = (NDD + TILE_M - 1) / TILE_M;  // 196
    dim3 tb(32, 8);

    // launch 0: fused weight prep (transpose + rna tf32)
    wprep_all_kernel<<<784, tb>>>(W1, W2, Wid, Wd, pW1T, pW2T, pWiT, pWdT);
    // launch 1: time projection
    tproj_kernel<<<1, 256>>>(t, Wt, bt, ptp);
    // launches 2-4: BN1(x) + SiLU -> a
    bn_stats_kernel<NI><<<STATS_BLOCKS, 256>>>(x, NN, ppart);
    bn_finalize_kernel<NI><<<1, NI>>>(ppart, STATS_BLOCKS, invn, g1, be1, pmv);
    {
        int n4 = NN * NI / 4;
        bn_apply_silu_kernel<NI><<<(n4 + 255) / 256, 256>>>((const float4*)x, pmv, (float4*)pa, n4);
    }
    // launch 5 (ncu-profiled): conv1 (+bias +FiLM fused) -> h
    conv_mma_kernel<64, 1><<<convGrid, 256, CONV_SMEM>>>(
        pa, nbr, pW1T, b1, nullptr, ptp, b_idx, nullptr, nullptr, ph, NN, KK);
    // ---- BN2(h) + SiLU -> a ----
    bn_stats_kernel<NFD><<<STATS_BLOCKS, 256>>>(ph, NN, ppart);
    bn_finalize_kernel<NFD><<<1, NFD>>>(ppart, STATS_BLOCKS, invn, g2, be2, pmv);
    {
        int n4 = NN * NFD / 4;
        bn_apply_silu_kernel<NFD><<<(n4 + 255) / 256, 256>>>((const float4*)ph, pmv, (float4*)pa, n4);
    }
    // ---- conv2 + fused idconv (+b2+bid) -> h2 ----
    conv_mma_kernel<128, 2><<<convGrid, 256, CONV_SMEM>>>(
        pa, nbr, pW2T, b2, bid, nullptr, nullptr, x, pWiT, ph2, NN, KK);
    // ---- strided down conv -> out ----
    conv_mma_kernel<128, 0><<<downGrid, 256, CONV_SMEM>>>(
        ph2, nbrd, pWdT, nullptr, nullptr, nullptr, nullptr, nullptr, nullptr, out, NDD, KDD);

    (void)in_sizes; (void)n_in; (void)out_size;
}

// round 7
// speedup vs baseline: 1.9593x; 1.6908x over previous
#include <cuda_runtime.h>
#include <cuda_fp16.h>
#include <math.h>
#include <stdint.h>

// ---------------- problem constants ----------------
#define NN   200000
#define NI   64
#define NFD  128
#define NE   256
#define BB   16
#define KK   27
#define KDD  8
#define NDD  (NN / 8)        // 25000

#define STATS_BLOCKS 512
#define TILE_M 128
#define CK 64                 // channels (halves) per chunk = 128B rows
#define ROWU 9                // padded row stride in 16B units (128B + 16B pad)
#define STAGE_BYTES (128 * ROWU * 16)   // 18432
#define CONV_SMEM (4 * STAGE_BYTES)     // A x2 + B x2 = 73728 B

// ---------------- scratch (device globals; no allocation allowed) ----------------
__device__ __half g_a  [(size_t)NN * NFD];   // fp16 activations (BN+SiLU output)
__device__ float  g_h  [(size_t)NN * NFD];   // conv1+film output (fp32)
__device__ __half g_h2 [(size_t)NN * NFD];   // conv2+idconv output (fp16)
__device__ __half g_xr [(size_t)NN * NI];    // fp16-rounded x (idconv input)
__device__ float  g_part[STATS_BLOCKS * 2 * NFD];
__device__ float  g_mv [2 * NFD];
__device__ float  g_tp [BB * 2 * NFD];
__device__ __half g_W1T[27 * 128 * 64];
__device__ __half g_W2T[27 * 128 * 128];
__device__ __half g_WiT[128 * 64];
__device__ __half g_WdT[8 * 128 * 128];

// ---------------- helpers ----------------
__device__ __forceinline__ float silu_f(float x) { return x / (1.0f + expf(-x)); }

__device__ __forceinline__ uint32_t smem_u32(const void* p) {
    uint32_t a;
    asm("{ .reg .u64 t; cvta.to.shared.u64 t, %1; cvt.u32.u64 %0, t; }" : "=r"(a) : "l"(p));
    return a;
}

__device__ __forceinline__ void ldsm4(uint32_t* d, uint32_t addr) {
    asm volatile("ldmatrix.sync.aligned.m8n8.x4.shared.b16 {%0,%1,%2,%3}, [%4];"
                 : "=r"(d[0]), "=r"(d[1]), "=r"(d[2]), "=r"(d[3]) : "r"(addr));
}

__device__ __forceinline__ void mma_f16(float* c, const uint32_t* a, const uint32_t* b) {
    asm volatile("mma.sync.aligned.m16n8k16.row.col.f32.f16.f16.f32 "
                 "{%0,%1,%2,%3}, {%4,%5,%6,%7}, {%8,%9}, {%0,%1,%2,%3};"
                 : "+f"(c[0]), "+f"(c[1]), "+f"(c[2]), "+f"(c[3])
                 : "r"(a[0]), "r"(a[1]), "r"(a[2]), "r"(a[3]), "r"(b[0]), "r"(b[1]));
}

// ---------------- fused weight prep: transpose [K][CI][128] -> fp16 [K][128][CI] ----------------
__global__ void wprep_all_kernel(const float* __restrict__ W1, const float* __restrict__ W2,
                                 const float* __restrict__ Wid, const float* __restrict__ Wd,
                                 __half* __restrict__ W1T, __half* __restrict__ W2T,
                                 __half* __restrict__ WiT, __half* __restrict__ WdT) {
    __shared__ float tile[32][33];
    int b = blockIdx.x;
    const float* W; __half* WT; int CI, k, cit, cot;
    if (b < 216)      { int r = b;       W = W1;  WT = W1T; CI = 64;  k = r / 8;  int q = r % 8;  cit = q / 4; cot = q % 4; }
    else if (b < 648) { int r = b - 216; W = W2;  WT = W2T; CI = 128; k = r / 16; int q = r % 16; cit = q / 4; cot = q % 4; }
    else if (b < 656) { int r = b - 648; W = Wid; WT = WiT; CI = 64;  k = 0;      cit = r / 4;    cot = r % 4; }
    else              { int r = b - 656; W = Wd;  WT = WdT; CI = 128; k = r / 16; int q = r % 16; cit = q / 4; cot = q % 4; }
    int ci0 = cit * 32, co0 = cot * 32;
    int tx = threadIdx.x, ty = threadIdx.y;   // 32 x 8
    #pragma unroll
    for (int j = 0; j < 4; ++j) {
        int ci = ci0 + ty + j * 8;
        tile[ty + j * 8][tx] = W[((size_t)k * CI + ci) * 128 + co0 + tx];
    }
    __syncthreads();
    #pragma unroll
    for (int j = 0; j < 4; ++j) {
        int co = co0 + ty + j * 8;
        WT[((size_t)k * 128 + co) * CI + ci0 + tx] = __float2half_rn(tile[tx][ty + j * 8]);
    }
}

// ---------------- time projection ----------------
__global__ void tproj_kernel(const float* __restrict__ T, const float* __restrict__ Wt,
                             const float* __restrict__ bt, float* __restrict__ tp) {
    __shared__ float ts[BB * NE];
    int t = threadIdx.x;
    for (int l = t; l < BB * NE; l += 256) ts[l] = silu_f(T[l]);
    __syncthreads();
    float acc[BB];
    #pragma unroll
    for (int b = 0; b < BB; ++b) acc[b] = 0.f;
    for (int e = 0; e < NE; ++e) {
        float w = Wt[e * 256 + t];
        #pragma unroll
        for (int b = 0; b < BB; ++b) acc[b] = fmaf(ts[b * NE + e], w, acc[b]);
    }
    float bias = bt[t];
    #pragma unroll
    for (int b = 0; b < BB; ++b) tp[b * 256 + t] = acc[b] + bias;
}

// ---------------- BN statistics ----------------
template<int C>
__global__ void bn_stats_kernel(const float* __restrict__ X, int n, float* __restrict__ part) {
    constexpr int G = 256 / C;
    __shared__ float sh[512];
    int t = threadIdx.x;
    int c = t % C, g = t / C;
    float s = 0.f, s2 = 0.f;
    for (int r = blockIdx.x * G + g; r < n; r += gridDim.x * G) {
        float v = X[(size_t)r * C + c];
        s += v; s2 += v * v;
    }
    sh[t] = s; sh[256 + t] = s2;
    __syncthreads();
    if (t < C) {
        float a = 0.f, b = 0.f;
        #pragma unroll
        for (int gg = 0; gg < G; ++gg) { a += sh[gg * C + t]; b += sh[256 + gg * C + t]; }
        part[blockIdx.x * (2 * C) + t]     = a;
        part[blockIdx.x * (2 * C) + C + t] = b;
    }
}

// parallel finalize: 512 threads, strided partial sums
template<int C>
__global__ void bn_finalize_kernel(const float* __restrict__ part, int nblocks, float invn,
                                   const float* __restrict__ g, const float* __restrict__ be,
                                   float* __restrict__ mv) {
    constexpr int G = 512 / C;
    __shared__ float sh[1024];
    int t = threadIdx.x;
    int c = t % C, gg = t / C;
    float s = 0.f, s2 = 0.f;
    for (int b = gg; b < nblocks; b += G) {
        s  += part[b * 2 * C + c];
        s2 += part[b * 2 * C + C + c];
    }
    sh[t] = s; sh[512 + t] = s2;
    __syncthreads();
    if (t < C) {
        float a = 0.f, bsum = 0.f;
        #pragma unroll
        for (int q = 0; q < G; ++q) { a += sh[q * C + t]; bsum += sh[512 + q * C + t]; }
        float mean = a * invn;
        float var  = bsum * invn - mean * mean;
        float istd = rsqrtf(var + 1e-5f);
        float A = istd * g[t];
        mv[t]     = A;
        mv[C + t] = be[t] - mean * A;
    }
}

// BN apply + SiLU -> fp16 (8 channels per thread, 16B store)
template<int C>
__global__ void bn_apply_silu_kernel(const float4* __restrict__ X, const float* __restrict__ mv,
                                     uint4* __restrict__ Y, int n8) {
    int i = blockIdx.x * 256 + threadIdx.x;
    if (i >= n8) return;
    int f = (i & (C / 8 - 1)) * 8;
    float4 v0 = X[2 * i], v1 = X[2 * i + 1];
    union { uint4 u; __half2 h[4]; } o;
    o.h[0] = __floats2half2_rn(silu_f(fmaf(v0.x, mv[f + 0], mv[C + f + 0])),
                               silu_f(fmaf(v0.y, mv[f + 1], mv[C + f + 1])));
    o.h[1] = __floats2half2_rn(silu_f(fmaf(v0.z, mv[f + 2], mv[C + f + 2])),
                               silu_f(fmaf(v0.w, mv[f + 3], mv[C + f + 3])));
    o.h[2] = __floats2half2_rn(silu_f(fmaf(v1.x, mv[f + 4], mv[C + f + 4])),
                               silu_f(fmaf(v1.y, mv[f + 5], mv[C + f + 5])));
    o.h[3] = __floats2half2_rn(silu_f(fmaf(v1.z, mv[f + 6], mv[C + f + 6])),
                               silu_f(fmaf(v1.w, mv[f + 7], mv[C + f + 7])));
    Y[i] = o.u;
}

// fp16 rounding copy (x -> xr)
__global__ void round_kernel(const float4* __restrict__ X, uint4* __restrict__ Y, int n8) {
    int i = blockIdx.x * 256 + threadIdx.x;
    if (i >= n8) return;
    float4 v0 = X[2 * i], v1 = X[2 * i + 1];
    union { uint4 u; __half2 h[4]; } o;
    o.h[0] = __floats2half2_rn(v0.x, v0.y);
    o.h[1] = __floats2half2_rn(v0.z, v0.w);
    o.h[2] = __floats2half2_rn(v1.x, v1.y);
    o.h[3] = __floats2half2_rn(v1.z, v1.w);
    Y[i] = o.u;
}

// ---------------- fp16 mma.sync gather-GEMM (sparse conv) ----------------
// MODE: 0 = plain fp32 out, 1 = bias + FiLM fp32 out, 2 = bias+bias2 + idconv chunk, fp16 out
struct Chunk {
    const __half* a;   // activation source (fp16)
    int aCIN;
    const int* nb;     // neighbor row (nullptr = identity)
    const __half* b;   // weight chunk base (pre-offset by cc), row stride brs
    int brs;
    int cc;
};

template<int CIN, int MODE>
__global__ __launch_bounds__(256, 2)
void conv_mma_kernel(const __half* __restrict__ X, const int* __restrict__ nbr,
                     const __half* __restrict__ BT, const float* __restrict__ bias,
                     const float* __restrict__ bias2, const float* __restrict__ tp,
                     const int* __restrict__ b_idx, const __half* __restrict__ Xid,
                     const __half* __restrict__ WiT,
                     void* __restrict__ outv, int M, int K) {
    extern __shared__ char sm[];
    const uint32_t smA = smem_u32(sm);                    // A: 2 x 18432 B
    const uint32_t smB = smA + 2 * STAGE_BYTES;           // B: 2 x 18432 B

    constexpr int CPK = CIN / CK;
    const int MAIN  = K * CPK;
    const int TOTAL = MAIN + ((MODE == 2) ? 1 : 0);

    const int t = threadIdx.x;
    const int lane = t & 31, w = t >> 5;
    const int warpM = w >> 2, warpN = w & 3;
    const int rowBase = blockIdx.x * TILE_M;

    // loader roles: 2 threads per row, 64B (32 halves) each
    const int lr = t >> 1;
    const int lh = t & 1;

    // ldmatrix per-lane address components
    const int aRow = warpM * 64 + (lane & 15);
    const int aSeg = lane >> 4;
    const int bRow = warpN * 32 + (lane & 7) + 8 * (lane >> 4);
    const int bSeg = (lane >> 3) & 1;

    float acc[4][4][4];
    #pragma unroll
    for (int i = 0; i < 4; ++i)
        #pragma unroll
        for (int j = 0; j < 4; ++j)
            #pragma unroll
            for (int q = 0; q < 4; ++q) acc[i][j][q] = 0.f;

    auto decode = [&](int c) -> Chunk {
        Chunk ch;
        if (MODE != 2 || c < MAIN) {
            int k  = c / CPK;
            int cc = (c - k * CPK) * CK;
            ch.a = X; ch.aCIN = CIN; ch.cc = cc;
            ch.nb = nbr + (size_t)k * M;
            ch.b = BT + ((size_t)k * 128) * CIN + cc; ch.brs = CIN;
        } else {
            ch.a = Xid; ch.aCIN = 64; ch.cc = 0;
            ch.nb = nullptr;
            ch.b = WiT; ch.brs = 64;
        }
        return ch;
    };

    uint4 va[4];
    auto ldA = [&](const Chunk& ch) {
        int row = rowBase + lr;
        int idx = -1;
        if (row < M) idx = ch.nb ? ch.nb[row] : row;
        if (idx >= 0) {
            const uint4* p = (const uint4*)(ch.a + (size_t)idx * ch.aCIN + ch.cc) + lh * 4;
            va[0] = p[0]; va[1] = p[1]; va[2] = p[2]; va[3] = p[3];
        } else {
            va[0] = va[1] = va[2] = va[3] = make_uint4(0, 0, 0, 0);
        }
    };
    auto stsA = [&](int bu) {
        char* dst = sm + bu * STAGE_BYTES + (lr * ROWU + lh * 4) * 16;
        #pragma unroll
        for (int j = 0; j < 4; ++j) ((uint4*)dst)[j] = va[j];
    };
    auto cpB = [&](const Chunk& ch, int bu) {
        uint32_t bd = smB + bu * STAGE_BYTES + (lr * ROWU + lh * 4) * 16;
        const char* gp = (const char*)(ch.b + (size_t)lr * ch.brs) + lh * 64;
        #pragma unroll
        for (int j = 0; j < 4; ++j)
            asm volatile("cp.async.ca.shared.global [%0], [%1], 16;"
                         :: "r"(bd + 16u * j), "l"(gp + 16 * j) : "memory");
        asm volatile("cp.async.commit_group;" ::: "memory");
    };

    // prologue
    {
        Chunk c0 = decode(0);
        ldA(c0);
        cpB(c0, 0);
    }

    for (int c = 0; c < TOTAL; ++c) {
        const int bu = c & 1;
        stsA(bu);
        asm volatile("cp.async.wait_group 0;" ::: "memory");
        __syncthreads();
        if (c + 1 < TOTAL) {
            Chunk cn = decode(c + 1);
            ldA(cn);
            cpB(cn, bu ^ 1);
        }
        // ---- compute chunk c (64 channels = 4 k16 steps) ----
        const uint32_t abuf = smA + bu * STAGE_BYTES;
        const uint32_t bbuf = smB + bu * STAGE_BYTES;
        #pragma unroll
        for (int kt = 0; kt < 4; ++kt) {
            uint32_t a[4][4];
            #pragma unroll
            for (int mt = 0; mt < 4; ++mt)
                ldsm4(a[mt], abuf + ((aRow + mt * 16) * ROWU + 2 * kt + aSeg) * 16);
            uint32_t b[4][2];
            #pragma unroll
            for (int ntp = 0; ntp < 2; ++ntp) {
                uint32_t d[4];
                ldsm4(d, bbuf + ((bRow + ntp * 16) * ROWU + 2 * kt + bSeg) * 16);
                b[2 * ntp][0] = d[0]; b[2 * ntp][1] = d[1];
                b[2 * ntp + 1][0] = d[2]; b[2 * ntp + 1][1] = d[3];
            }
            #pragma unroll
            for (int mt = 0; mt < 4; ++mt)
                #pragma unroll
                for (int nt = 0; nt < 4; ++nt)
                    mma_f16(acc[mt][nt], a[mt], b[nt]);
        }
    }

    // ---- epilogue ----
    #pragma unroll
    for (int mt = 0; mt < 4; ++mt) {
        int row0 = rowBase + warpM * 64 + mt * 16 + (lane >> 2);
        #pragma unroll
        for (int hr = 0; hr < 2; ++hr) {
            int row = row0 + 8 * hr;
            if (row >= M) continue;
            const float* tpr = (MODE == 1) ? (tp + b_idx[row] * 256) : nullptr;
            #pragma unroll
            for (int nt = 0; nt < 4; ++nt) {
                int col = warpN * 32 + nt * 8 + 2 * (lane & 3);
                float v0 = acc[mt][nt][2 * hr + 0];
                float v1 = acc[mt][nt][2 * hr + 1];
                if (MODE == 1) {
                    v0 = (v0 + bias[col])     * (1.f + tpr[col])     + tpr[128 + col];
                    v1 = (v1 + bias[col + 1]) * (1.f + tpr[col + 1]) + tpr[129 + col];
                    float* out = (float*)outv;
                    *(float2*)(out + (size_t)row * 128 + col) = make_float2(v0, v1);
                } else if (MODE == 2) {
                    v0 += bias[col] + bias2[col];
                    v1 += bias[col + 1] + bias2[col + 1];
                    __half* out = (__half*)outv;
                    *(__half2*)(out + (size_t)row * 128 + col) = __floats2half2_rn(v0, v1);
                } else {
                    float* out = (float*)outv;
                    *(float2*)(out + (size_t)row * 128 + col) = make_float2(v0, v1);
                }
            }
        }
    }
}

// ---------------- launch ----------------
extern "C" void kernel_launch(void* const* d_in, const int* in_sizes, int n_in,
                              void* d_out, int out_size) {
    const float* x     = (const float*)d_in[0];
    const float* t     = (const float*)d_in[1];
    const int*   b_idx = (const int*)  d_in[2];
    const int*   nbr   = (const int*)  d_in[3];
    const int*   nbrd  = (const int*)  d_in[4];
    const float* g1    = (const float*)d_in[5];
    const float* be1   = (const float*)d_in[6];
    const float* W1    = (const float*)d_in[7];
    const float* b1    = (const float*)d_in[8];
    const float* Wt    = (const float*)d_in[9];
    const float* bt    = (const float*)d_in[10];
    const float* g2    = (const float*)d_in[11];
    const float* be2   = (const float*)d_in[12];
    const float* W2    = (const float*)d_in[13];
    const float* b2    = (const float*)d_in[14];
    const float* Wid   = (const float*)d_in[15];
    const float* bid   = (const float*)d_in[16];
    const float* Wd    = (const float*)d_in[17];
    float* out = (float*)d_out;

    __half *pa, *ph2, *pxr, *pW1T, *pW2T, *pWiT, *pWdT;
    float *ph, *ppart, *pmv, *ptp;
    cudaGetSymbolAddress((void**)&pa,    g_a);
    cudaGetSymbolAddress((void**)&ph,    g_h);
    cudaGetSymbolAddress((void**)&ph2,   g_h2);
    cudaGetSymbolAddress((void**)&pxr,   g_xr);
    cudaGetSymbolAddress((void**)&ppart, g_part);
    cudaGetSymbolAddress((void**)&pmv,   g_mv);
    cudaGetSymbolAddress((void**)&ptp,   g_tp);
    cudaGetSymbolAddress((void**)&pW1T,  g_W1T);
    cudaGetSymbolAddress((void**)&pW2T,  g_W2T);
    cudaGetSymbolAddress((void**)&pWiT,  g_WiT);
    cudaGetSymbolAddress((void**)&pWdT,  g_WdT);

    cudaFuncSetAttribute(conv_mma_kernel<64, 1>,  cudaFuncAttributeMaxDynamicSharedMemorySize, CONV_SMEM);
    cudaFuncSetAttribute(conv_mma_kernel<128, 2>, cudaFuncAttributeMaxDynamicSharedMemorySize, CONV_SMEM);
    cudaFuncSetAttribute(conv_mma_kernel<128, 0>, cudaFuncAttributeMaxDynamicSharedMemorySize, CONV_SMEM);

    const float invn = 1.0f / (float)NN;
    const int convGrid = (NN + TILE_M - 1) / TILE_M;   // 1563
    const int downGrid = (NDD + TILE_M - 1) / TILE_M;  // 196
    dim3 tb(32, 8);

    // weight prep (transpose + fp16)
    wprep_all_kernel<<<784, tb>>>(W1, W2, Wid, Wd, pW1T, pW2T, pWiT, pWdT);
    // time projection
    tproj_kernel<<<1, 256>>>(t, Wt, bt, ptp);
    // BN1(x) + SiLU -> a (fp16)
    bn_stats_kernel<NI><<<STATS_BLOCKS, 256>>>(x, NN, ppart);
    bn_finalize_kernel<NI><<<1, 512>>>(ppart, STATS_BLOCKS, invn, g1, be1, pmv);
    {
        int n8 = NN * NI / 8;
        bn_apply_silu_kernel<NI><<<(n8 + 255) / 256, 256>>>((const float4*)x, pmv, (uint4*)pa, n8);
    }
    // conv1 (+bias +FiLM fused) -> h (fp32)
    conv_mma_kernel<64, 1><<<convGrid, 256, CONV_SMEM>>>(
        pa, nbr, pW1T, b1, nullptr, ptp, b_idx, nullptr, nullptr, ph, NN, KK);
    // round x -> xr (fp16) for idconv
    {
        int n8 = NN * NI / 8;
        round_kernel<<<(n8 + 255) / 256, 256>>>((const float4*)x, (uint4*)pxr, n8);
    }
    // BN2(h) + SiLU -> a (fp16)
    bn_stats_kernel<NFD><<<STATS_BLOCKS, 256>>>(ph, NN, ppart);
    bn_finalize_kernel<NFD><<<1, 512>>>(ppart, STATS_BLOCKS, invn, g2, be2, pmv);
    {
        int n8 = NN * NFD / 8;
        bn_apply_silu_kernel<NFD><<<(n8 + 255) / 256, 256>>>((const float4*)ph, pmv, (uint4*)pa, n8);
    }
    // conv2 + fused idconv (+b2+bid) -> h2 (fp16)
    conv_mma_kernel<128, 2><<<convGrid, 256, CONV_SMEM>>>(
        pa, nbr, pW2T, b2, bid, nullptr, nullptr, pxr, pWiT, ph2, NN, KK);
    // strided down conv -> out (fp32)
    conv_mma_kernel<128, 0><<<downGrid, 256, CONV_SMEM>>>(
        ph2, nbrd, pWdT, nullptr, nullptr, nullptr, nullptr, nullptr, nullptr, out, NDD, KDD);

    (void)in_sizes; (void)n_in; (void)out_size;
}

// round 8
// speedup vs baseline: 2.1833x; 1.1143x over previous
#include <cuda_runtime.h>
#include <cuda_fp16.h>
#include <math.h>
#include <stdint.h>

// ---------------- problem constants ----------------
#define NN   200000
#define NI   64
#define NFD  128
#define NE   256
#define BB   16
#define KK   27
#define KDD  8
#define NDD  (NN / 8)        // 25000

#define STATS_BLOCKS 512
#define TILE_M 128
#define CK 64                 // channels (halves) per chunk = 128B rows
#define ROWU 9                // padded row stride in 16B units (128B + 16B pad)
#define STAGE_BYTES (128 * ROWU * 16)   // 18432
#define CONV_SMEM (4 * STAGE_BYTES)     // A x2 + B x2 = 73728 B
#define NCTA 1563             // conv grid

// ---------------- scratch (device globals; no allocation allowed) ----------------
__device__ __half g_a  [(size_t)NN * NFD];   // fp16 activations (BN+SiLU output)
__device__ float  g_h  [(size_t)NN * NFD];   // conv1+film output (fp32)
__device__ __half g_h2 [(size_t)NN * NFD];   // conv2+idconv output (fp16)
__device__ __half g_xr [(size_t)NN * NI];    // fp16-rounded x (idconv input)
__device__ float  g_part[STATS_BLOCKS * 2 * NI];
__device__ float  g_cpart[(size_t)NCTA * 256];   // per-CTA conv1 stats partials
__device__ float  g_mv [2 * NFD];
__device__ float  g_tp [BB * 2 * NFD];
__device__ __half g_W1T[27 * 128 * 64];
__device__ __half g_W2T[27 * 128 * 128];
__device__ __half g_WiT[128 * 64];
__device__ __half g_WdT[8 * 128 * 128];

// ---------------- helpers ----------------
__device__ __forceinline__ float silu_f(float x) { return x / (1.0f + expf(-x)); }

__device__ __forceinline__ uint32_t smem_u32(const void* p) {
    uint32_t a;
    asm("{ .reg .u64 t; cvta.to.shared.u64 t, %1; cvt.u32.u64 %0, t; }" : "=r"(a) : "l"(p));
    return a;
}

__device__ __forceinline__ void ldsm4(uint32_t* d, uint32_t addr) {
    asm volatile("ldmatrix.sync.aligned.m8n8.x4.shared.b16 {%0,%1,%2,%3}, [%4];"
                 : "=r"(d[0]), "=r"(d[1]), "=r"(d[2]), "=r"(d[3]) : "r"(addr));
}

__device__ __forceinline__ void mma_f16(float* c, const uint32_t* a, const uint32_t* b) {
    asm volatile("mma.sync.aligned.m16n8k16.row.col.f32.f16.f16.f32 "
                 "{%0,%1,%2,%3}, {%4,%5,%6,%7}, {%8,%9}, {%0,%1,%2,%3};"
                 : "+f"(c[0]), "+f"(c[1]), "+f"(c[2]), "+f"(c[3])
                 : "r"(a[0]), "r"(a[1]), "r"(a[2]), "r"(a[3]), "r"(b[0]), "r"(b[1]));
}

// ---------------- fused prologue: bn_stats(x) | weight prep | tproj | round x ----------------
// blocks [0,512): bn_stats<64> on x
// blocks [512,1296): weight transpose+fp16 (784 tiles)
// block 1296: tproj
// blocks [1297, 1297+6250): round x -> xr fp16
__global__ void prologue_kernel(const float* __restrict__ x,
                                const float* __restrict__ T, const float* __restrict__ Wt,
                                const float* __restrict__ bt,
                                const float* __restrict__ W1, const float* __restrict__ W2,
                                const float* __restrict__ Wid, const float* __restrict__ Wd,
                                float* __restrict__ part, float* __restrict__ tp,
                                __half* __restrict__ W1T, __half* __restrict__ W2T,
                                __half* __restrict__ WiT, __half* __restrict__ WdT,
                                uint4* __restrict__ xr) {
    const int blk = blockIdx.x;
    const int t = threadIdx.x;
    if (blk < 512) {
        // ---- bn_stats on x (C=64) ----
        constexpr int C = NI, G = 256 / C;
        __shared__ float sh[512];
        int c = t % C, g = t / C;
        float s = 0.f, s2 = 0.f;
        for (int r = blk * G + g; r < NN; r += 512 * G) {
            float v = x[(size_t)r * C + c];
            s += v; s2 += v * v;
        }
        sh[t] = s; sh[256 + t] = s2;
        __syncthreads();
        if (t < C) {
            float a = 0.f, b = 0.f;
            #pragma unroll
            for (int gg = 0; gg < G; ++gg) { a += sh[gg * C + t]; b += sh[256 + gg * C + t]; }
            part[blk * (2 * C) + t]     = a;
            part[blk * (2 * C) + C + t] = b;
        }
    } else if (blk < 1296) {
        // ---- weight prep ----
        __shared__ float tile[32][33];
        int b = blk - 512;
        const float* W; __half* WT; int CI, k, cit, cot;
        if (b < 216)      { int r = b;       W = W1;  WT = W1T; CI = 64;  k = r / 8;  int q = r % 8;  cit = q / 4; cot = q % 4; }
        else if (b < 648) { int r = b - 216; W = W2;  WT = W2T; CI = 128; k = r / 16; int q = r % 16; cit = q / 4; cot = q % 4; }
        else if (b < 656) { int r = b - 648; W = Wid; WT = WiT; CI = 64;  k = 0;      cit = r / 4;    cot = r % 4; }
        else              { int r = b - 656; W = Wd;  WT = WdT; CI = 128; k = r / 16; int q = r % 16; cit = q / 4; cot = q % 4; }
        int ci0 = cit * 32, co0 = cot * 32;
        int tx = t & 31, ty = t >> 5;
        #pragma unroll
        for (int j = 0; j < 4; ++j) {
            int ci = ci0 + ty + j * 8;
            tile[ty + j * 8][tx] = W[((size_t)k * CI + ci) * 128 + co0 + tx];
        }
        __syncthreads();
        #pragma unroll
        for (int j = 0; j < 4; ++j) {
            int co = co0 + ty + j * 8;
            WT[((size_t)k * 128 + co) * CI + ci0 + tx] = __float2half_rn(tile[tx][ty + j * 8]);
        }
    } else if (blk == 1296) {
        // ---- time projection ----
        __shared__ float ts[BB * NE];
        for (int l = t; l < BB * NE; l += 256) ts[l] = silu_f(T[l]);
        __syncthreads();
        float acc[BB];
        #pragma unroll
        for (int b = 0; b < BB; ++b) acc[b] = 0.f;
        for (int e = 0; e < NE; ++e) {
            float w = Wt[e * 256 + t];
            #pragma unroll
            for (int b = 0; b < BB; ++b) acc[b] = fmaf(ts[b * NE + e], w, acc[b]);
        }
        float bias = bt[t];
        #pragma unroll
        for (int b = 0; b < BB; ++b) tp[b * 256 + t] = acc[b] + bias;
    } else {
        // ---- round x -> fp16 xr ----
        int i = (blk - 1297) * 256 + t;
        int n8 = NN * NI / 8;
        if (i < n8) {
            const float4* X = (const float4*)x;
            float4 v0 = X[2 * i], v1 = X[2 * i + 1];
            union { uint4 u; __half2 h[4]; } o;
            o.h[0] = __floats2half2_rn(v0.x, v0.y);
            o.h[1] = __floats2half2_rn(v0.z, v0.w);
            o.h[2] = __floats2half2_rn(v1.x, v1.y);
            o.h[3] = __floats2half2_rn(v1.z, v1.w);
            xr[i] = o.u;
        }
    }
}

// ---------------- BN finalize (from stats blocks) ----------------
template<int C>
__global__ void bn_finalize_kernel(const float* __restrict__ part, int nblocks, float invn,
                                   const float* __restrict__ g, const float* __restrict__ be,
                                   float* __restrict__ mv) {
    constexpr int G = 512 / C;
    __shared__ float sh[1024];
    int t = threadIdx.x;
    int c = t % C, gg = t / C;
    float s = 0.f, s2 = 0.f;
    for (int b = gg; b < nblocks; b += G) {
        s  += part[b * 2 * C + c];
        s2 += part[b * 2 * C + C + c];
    }
    sh[t] = s; sh[512 + t] = s2;
    __syncthreads();
    if (t < C) {
        float a = 0.f, bsum = 0.f;
        #pragma unroll
        for (int q = 0; q < G; ++q) { a += sh[q * C + t]; bsum += sh[512 + q * C + t]; }
        float mean = a * invn;
        float var  = bsum * invn - mean * mean;
        float istd = rsqrtf(var + 1e-5f);
        float A = istd * g[t];
        mv[t]     = A;
        mv[C + t] = be[t] - mean * A;
    }
}

// ---------------- BN2 finalize from per-CTA conv1 partials ----------------
__global__ void bn_finalize_cpart_kernel(const float* __restrict__ cpart, float invn,
                                         const float* __restrict__ g, const float* __restrict__ be,
                                         float* __restrict__ mv) {
    __shared__ float sh[1024];
    __shared__ float tot[256];
    int t = threadIdx.x;             // 1024 threads
    int c = t & 255, gg = t >> 8;    // 4 groups
    float s = 0.f;
    for (int b = gg; b < NCTA; b += 4) s += cpart[(size_t)b * 256 + c];
    sh[t] = s;
    __syncthreads();
    if (t < 256) tot[t] = sh[t] + sh[256 + t] + sh[512 + t] + sh[768 + t];
    __syncthreads();
    if (t < 128) {
        float mean = tot[t] * invn;
        float var  = tot[128 + t] * invn - mean * mean;
        float istd = rsqrtf(var + 1e-5f);
        float A = istd * g[t];
        mv[t]       = A;
        mv[128 + t] = be[t] - mean * A;
    }
}

// ---------------- BN apply + SiLU -> fp16 ----------------
template<int C>
__global__ void bn_apply_silu_kernel(const float4* __restrict__ X, const float* __restrict__ mv,
                                     uint4* __restrict__ Y, int n8) {
    int i = blockIdx.x * 256 + threadIdx.x;
    if (i >= n8) return;
    int f = (i & (C / 8 - 1)) * 8;
    float4 v0 = X[2 * i], v1 = X[2 * i + 1];
    union { uint4 u; __half2 h[4]; } o;
    o.h[0] = __floats2half2_rn(silu_f(fmaf(v0.x, mv[f + 0], mv[C + f + 0])),
                               silu_f(fmaf(v0.y, mv[f + 1], mv[C + f + 1])));
    o.h[1] = __floats2half2_rn(silu_f(fmaf(v0.z, mv[f + 2], mv[C + f + 2])),
                               silu_f(fmaf(v0.w, mv[f + 3], mv[C + f + 3])));
    o.h[2] = __floats2half2_rn(silu_f(fmaf(v1.x, mv[f + 4], mv[C + f + 4])),
                               silu_f(fmaf(v1.y, mv[f + 5], mv[C + f + 5])));
    o.h[3] = __floats2half2_rn(silu_f(fmaf(v1.z, mv[f + 6], mv[C + f + 6])),
                               silu_f(fmaf(v1.w, mv[f + 7], mv[C + f + 7])));
    Y[i] = o.u;
}

// ---------------- fp16 mma.sync gather-GEMM (sparse conv) ----------------
// MODE: 0 = plain fp32 out, 1 = bias + FiLM fp32 out + per-CTA stats, 2 = bias+bias2 + idconv, fp16 out
struct Chunk {
    const __half* a;
    int aCIN;
    const int* nb;
    const __half* b;
    int brs;
    int cc;
};

template<int CIN, int MODE>
__global__ __launch_bounds__(256, 2)
void conv_mma_kernel(const __half* __restrict__ X, const int* __restrict__ nbr,
                     const __half* __restrict__ BT, const float* __restrict__ bias,
                     const float* __restrict__ bias2, const float* __restrict__ tp,
                     const int* __restrict__ b_idx, const __half* __restrict__ Xid,
                     const __half* __restrict__ WiT, float* __restrict__ cpart,
                     void* __restrict__ outv, int M, int K) {
    extern __shared__ char sm[];
    const uint32_t smA = smem_u32(sm);                    // A: 2 x 18432 B
    const uint32_t smB = smA + 2 * STAGE_BYTES;           // B: 2 x 18432 B

    constexpr int CPK = CIN / CK;
    const int MAIN  = K * CPK;
    const int TOTAL = MAIN + ((MODE == 2) ? 1 : 0);

    const int t = threadIdx.x;
    const int lane = t & 31, w = t >> 5;
    const int warpM = w >> 2, warpN = w & 3;
    const int rowBase = blockIdx.x * TILE_M;

    const int lr = t >> 1;
    const int lh = t & 1;

    const int aRow = warpM * 64 + (lane & 15);
    const int aSeg = lane >> 4;
    const int bRow = warpN * 32 + (lane & 7) + 8 * (lane >> 4);
    const int bSeg = (lane >> 3) & 1;

    float acc[4][4][4];
    #pragma unroll
    for (int i = 0; i < 4; ++i)
        #pragma unroll
        for (int j = 0; j < 4; ++j)
            #pragma unroll
            for (int q = 0; q < 4; ++q) acc[i][j][q] = 0.f;

    auto decode = [&](int c) -> Chunk {
        Chunk ch;
        if (MODE != 2 || c < MAIN) {
            int k  = c / CPK;
            int cc = (c - k * CPK) * CK;
            ch.a = X; ch.aCIN = CIN; ch.cc = cc;
            ch.nb = nbr + (size_t)k * M;
            ch.b = BT + ((size_t)k * 128) * CIN + cc; ch.brs = CIN;
        } else {
            ch.a = Xid; ch.aCIN = 64; ch.cc = 0;
            ch.nb = nullptr;
            ch.b = WiT; ch.brs = 64;
        }
        return ch;
    };

    uint4 va[4];
    auto ldA = [&](const Chunk& ch) {
        int row = rowBase + lr;
        int idx = -1;
        if (row < M) idx = ch.nb ? ch.nb[row] : row;
        if (idx >= 0) {
            const uint4* p = (const uint4*)(ch.a + (size_t)idx * ch.aCIN + ch.cc) + lh * 4;
            va[0] = p[0]; va[1] = p[1]; va[2] = p[2]; va[3] = p[3];
        } else {
            va[0] = va[1] = va[2] = va[3] = make_uint4(0, 0, 0, 0);
        }
    };
    auto stsA = [&](int bu) {
        char* dst = sm + bu * STAGE_BYTES + (lr * ROWU + lh * 4) * 16;
        #pragma unroll
        for (int j = 0; j < 4; ++j) ((uint4*)dst)[j] = va[j];
    };
    auto cpB = [&](const Chunk& ch, int bu) {
        uint32_t bd = smB + bu * STAGE_BYTES + (lr * ROWU + lh * 4) * 16;
        const char* gp = (const char*)(ch.b + (size_t)lr * ch.brs) + lh * 64;
        #pragma unroll
        for (int j = 0; j < 4; ++j)
            asm volatile("cp.async.ca.shared.global [%0], [%1], 16;"
                         :: "r"(bd + 16u * j), "l"(gp + 16 * j) : "memory");
        asm volatile("cp.async.commit_group;" ::: "memory");
    };

    {
        Chunk c0 = decode(0);
        ldA(c0);
        cpB(c0, 0);
    }

    for (int c = 0; c < TOTAL; ++c) {
        const int bu = c & 1;
        stsA(bu);
        asm volatile("cp.async.wait_group 0;" ::: "memory");
        __syncthreads();
        if (c + 1 < TOTAL) {
            Chunk cn = decode(c + 1);
            ldA(cn);
            cpB(cn, bu ^ 1);
        }
        const uint32_t abuf = smA + bu * STAGE_BYTES;
        const uint32_t bbuf = smB + bu * STAGE_BYTES;
        #pragma unroll
        for (int kt = 0; kt < 4; ++kt) {
            uint32_t a[4][4];
            #pragma unroll
            for (int mt = 0; mt < 4; ++mt)
                ldsm4(a[mt], abuf + ((aRow + mt * 16) * ROWU + 2 * kt + aSeg) * 16);
            uint32_t b[4][2];
            #pragma unroll
            for (int ntp = 0; ntp < 2; ++ntp) {
                uint32_t d[4];
                ldsm4(d, bbuf + ((bRow + ntp * 16) * ROWU + 2 * kt + bSeg) * 16);
                b[2 * ntp][0] = d[0]; b[2 * ntp][1] = d[1];
                b[2 * ntp + 1][0] = d[2]; b[2 * ntp + 1][1] = d[3];
            }
            #pragma unroll
            for (int mt = 0; mt < 4; ++mt)
                #pragma unroll
                for (int nt = 0; nt < 4; ++nt)
                    mma_f16(acc[mt][nt], a[mt], b[nt]);
        }
    }

    // ---- epilogue ----
    float ss[8], sq[8];
    if (MODE == 1) {
        #pragma unroll
        for (int q = 0; q < 8; ++q) { ss[q] = 0.f; sq[q] = 0.f; }
    }
    #pragma unroll
    for (int mt = 0; mt < 4; ++mt) {
        int row0 = rowBase + warpM * 64 + mt * 16 + (lane >> 2);
        #pragma unroll
        for (int hr = 0; hr < 2; ++hr) {
            int row = row0 + 8 * hr;
            if (row >= M) continue;
            const float* tpr = (MODE == 1) ? (tp + b_idx[row] * 256) : nullptr;
            #pragma unroll
            for (int nt = 0; nt < 4; ++nt) {
                int col = warpN * 32 + nt * 8 + 2 * (lane & 3);
                float v0 = acc[mt][nt][2 * hr + 0];
                float v1 = acc[mt][nt][2 * hr + 1];
                if (MODE == 1) {
                    v0 = (v0 + bias[col])     * (1.f + tpr[col])     + tpr[128 + col];
                    v1 = (v1 + bias[col + 1]) * (1.f + tpr[col + 1]) + tpr[129 + col];
                    ss[2 * nt]     += v0; sq[2 * nt]     += v0 * v0;
                    ss[2 * nt + 1] += v1; sq[2 * nt + 1] += v1 * v1;
                    float* out = (float*)outv;
                    *(float2*)(out + (size_t)row * 128 + col) = make_float2(v0, v1);
                } else if (MODE == 2) {
                    v0 += bias[col] + bias2[col];
                    v1 += bias[col + 1] + bias2[col + 1];
                    __half* out = (__half*)outv;
                    *(__half2*)(out + (size_t)row * 128 + col) = __floats2half2_rn(v0, v1);
                } else {
                    float* out = (float*)outv;
                    *(float2*)(out + (size_t)row * 128 + col) = make_float2(v0, v1);
                }
            }
        }
    }

    if (MODE == 1) {
        // deterministic per-CTA channel stats: butterfly over lane bits 2..4
        #pragma unroll
        for (int q = 0; q < 8; ++q) {
            #pragma unroll
            for (int off = 4; off <= 16; off <<= 1) {
                ss[q] += __shfl_xor_sync(0xffffffff, ss[q], off);
                sq[q] += __shfl_xor_sync(0xffffffff, sq[q], off);
            }
        }
        __syncthreads();                 // A/B smem no longer needed
        float* sstat = (float*)sm;       // [2 warpM][256]
        if (lane < 4) {
            #pragma unroll
            for (int nt = 0; nt < 4; ++nt)
                #pragma unroll
                for (int p = 0; p < 2; ++p) {
                    int col = warpN * 32 + nt * 8 + 2 * lane + p;
                    sstat[warpM * 256 + col]       = ss[2 * nt + p];
                    sstat[warpM * 256 + 128 + col] = sq[2 * nt + p];
                }
        }
        __syncthreads();
        if (t < 256)
            cpart[(size_t)blockIdx.x * 256 + t] = sstat[t] + sstat[256 + t];
    }
}

// ---------------- launch ----------------
extern "C" void kernel_launch(void* const* d_in, const int* in_sizes, int n_in,
                              void* d_out, int out_size) {
    const float* x     = (const float*)d_in[0];
    const float* t     = (const float*)d_in[1];
    const int*   b_idx = (const int*)  d_in[2];
    const int*   nbr   = (const int*)  d_in[3];
    const int*   nbrd  = (const int*)  d_in[4];
    const float* g1    = (const float*)d_in[5];
    const float* be1   = (const float*)d_in[6];
    const float* W1    = (const float*)d_in[7];
    const float* b1    = (const float*)d_in[8];
    const float* Wt    = (const float*)d_in[9];
    const float* bt    = (const float*)d_in[10];
    const float* g2    = (const float*)d_in[11];
    const float* be2   = (const float*)d_in[12];
    const float* W2    = (const float*)d_in[13];
    const float* b2    = (const float*)d_in[14];
    const float* Wid   = (const float*)d_in[15];
    const float* bid   = (const float*)d_in[16];
    const float* Wd    = (const float*)d_in[17];
    float* out = (float*)d_out;

    __half *pa, *ph2, *pxr, *pW1T, *pW2T, *pWiT, *pWdT;
    float *ph, *ppart, *pcpart, *pmv, *ptp;
    cudaGetSymbolAddress((void**)&pa,     g_a);
    cudaGetSymbolAddress((void**)&ph,     g_h);
    cudaGetSymbolAddress((void**)&ph2,    g_h2);
    cudaGetSymbolAddress((void**)&pxr,    g_xr);
    cudaGetSymbolAddress((void**)&ppart,  g_part);
    cudaGetSymbolAddress((void**)&pcpart, g_cpart);
    cudaGetSymbolAddress((void**)&pmv,    g_mv);
    cudaGetSymbolAddress((void**)&ptp,    g_tp);
    cudaGetSymbolAddress((void**)&pW1T,   g_W1T);
    cudaGetSymbolAddress((void**)&pW2T,   g_W2T);
    cudaGetSymbolAddress((void**)&pWiT,   g_WiT);
    cudaGetSymbolAddress((void**)&pWdT,   g_WdT);

    cudaFuncSetAttribute(conv_mma_kernel<64, 1>,  cudaFuncAttributeMaxDynamicSharedMemorySize, CONV_SMEM);
    cudaFuncSetAttribute(conv_mma_kernel<128, 2>, cudaFuncAttributeMaxDynamicSharedMemorySize, CONV_SMEM);
    cudaFuncSetAttribute(conv_mma_kernel<128, 0>, cudaFuncAttributeMaxDynamicSharedMemorySize, CONV_SMEM);

    const float invn = 1.0f / (float)NN;
    const int downGrid = (NDD + TILE_M - 1) / TILE_M;  // 196

    // launch 0: fused prologue (stats1 | wprep | tproj | round x)
    prologue_kernel<<<1297 + 6250, 256>>>(x, t, Wt, bt, W1, W2, Wid, Wd,
                                          ppart, ptp, pW1T, pW2T, pWiT, pWdT, (uint4*)pxr);
    // launch 1: BN1 finalize
    bn_finalize_kernel<NI><<<1, 512>>>(ppart, STATS_BLOCKS, invn, g1, be1, pmv);
    // launch 2: BN1 apply + SiLU -> a (fp16)
    {
        int n8 = NN * NI / 8;
        bn_apply_silu_kernel<NI><<<(n8 + 255) / 256, 256>>>((const float4*)x, pmv, (uint4*)pa, n8);
    }
    // launch 3 (ncu-profiled): conv1 (+bias +FiLM + stats) -> h (fp32)
    conv_mma_kernel<64, 1><<<NCTA, 256, CONV_SMEM>>>(
        pa, nbr, pW1T, b1, nullptr, ptp, b_idx, nullptr, nullptr, pcpart, ph, NN, KK);
    // launch 4: BN2 finalize from conv1 partials
    bn_finalize_cpart_kernel<<<1, 1024>>>(pcpart, invn, g2, be2, pmv);
    // launch 5: BN2 apply + SiLU -> a (fp16)
    {
        int n8 = NN * NFD / 8;
        bn_apply_silu_kernel<NFD><<<(n8 + 255) / 256, 256>>>((const float4*)ph, pmv, (uint4*)pa, n8);
    }
    // launch 6: conv2 + fused idconv (+b2+bid) -> h2 (fp16)
    conv_mma_kernel<128, 2><<<NCTA, 256, CONV_SMEM>>>(
        pa, nbr, pW2T, b2, bid, nullptr, nullptr, pxr, pWiT, nullptr, ph2, NN, KK);
    // launch 7: strided down conv -> out (fp32)
    conv_mma_kernel<128, 0><<<downGrid, 256, CONV_SMEM>>>(
        ph2, nbrd, pWdT, nullptr, nullptr, nullptr, nullptr, nullptr, nullptr, nullptr,
        out, NDD, KDD);

    (void)in_sizes; (void)n_in; (void)out_size;
}

// round 9
// speedup vs baseline: 2.5201x; 1.1542x over previous
#include <cuda_runtime.h>
#include <cuda_fp16.h>
#include <math.h>
#include <stdint.h>

// ---------------- problem constants ----------------
#define NN   200000
#define NI   64
#define NFD  128
#define NE   256
#define BB   16
#define KK   27
#define KDD  8
#define NDD  (NN / 8)        // 25000

#define STATS_BLOCKS 512
#define TILE_M 128
#define ROWU 9                // padded A row stride in 16B units (128B + 16B pad)
#define STAGE_BYTES (128 * ROWU * 16)   // 18432
#define CONV_SMEM (2 * STAGE_BYTES)     // A only, 2 stages = 36864 B
#define NCTA 1563             // conv grid
#define NCHUNK 98             // 27 (conv1) + 54 (conv2) + 1 (idconv) + 16 (down)

// ---------------- scratch (device globals; no allocation allowed) ----------------
__device__ __half g_a  [(size_t)NN * NFD];   // fp16 activations (BN+SiLU output)
__device__ float  g_h  [(size_t)NN * NFD];   // conv1+film output (fp32)
__device__ __half g_h2 [(size_t)NN * NFD];   // conv2+idconv output (fp16)
__device__ __half g_xr [(size_t)NN * NI];    // fp16-rounded x (idconv input)
__device__ float  g_part[STATS_BLOCKS * 2 * NI];
__device__ float  g_cpart[(size_t)NCTA * 256];   // per-CTA conv1 stats partials
__device__ float  g_mv [2 * NFD];
__device__ float  g_tp [BB * 2 * NFD];
__device__ uint2  g_PB [(size_t)NCHUNK * 2048];  // permuted B fragments (16KB/chunk)

// ---------------- helpers ----------------
__device__ __forceinline__ float silu_f(float x) { return x / (1.0f + expf(-x)); }

__device__ __forceinline__ uint32_t smem_u32(const void* p) {
    uint32_t a;
    asm("{ .reg .u64 t; cvta.to.shared.u64 t, %1; cvt.u32.u64 %0, t; }" : "=r"(a) : "l"(p));
    return a;
}

__device__ __forceinline__ void ldsm4(uint32_t* d, uint32_t addr) {
    asm volatile("ldmatrix.sync.aligned.m8n8.x4.shared.b16 {%0,%1,%2,%3}, [%4];"
                 : "=r"(d[0]), "=r"(d[1]), "=r"(d[2]), "=r"(d[3]) : "r"(addr));
}

__device__ __forceinline__ void mma_f16(float* c, const uint32_t* a, uint32_t b0, uint32_t b1) {
    asm volatile("mma.sync.aligned.m16n8k16.row.col.f32.f16.f16.f32 "
                 "{%0,%1,%2,%3}, {%4,%5,%6,%7}, {%8,%9}, {%0,%1,%2,%3};"
                 : "+f"(c[0]), "+f"(c[1]), "+f"(c[2]), "+f"(c[3])
                 : "r"(a[0]), "r"(a[1]), "r"(a[2]), "r"(a[3]), "r"(b0), "r"(b1));
}

// ---------------- fused prologue ----------------
// blocks [0,512): bn_stats<64> on x
// blocks [512,904): B fragment prep (98 chunks x 4 quarter-blocks)
// block 904: tproj
// blocks [905, 905+6250): round x -> xr fp16
__global__ void prologue_kernel(const float* __restrict__ x,
                                const float* __restrict__ T, const float* __restrict__ Wt,
                                const float* __restrict__ bt,
                                const float* __restrict__ W1, const float* __restrict__ W2,
                                const float* __restrict__ Wid, const float* __restrict__ Wd,
                                float* __restrict__ part, float* __restrict__ tp,
                                uint2* __restrict__ PB, uint4* __restrict__ xr) {
    const int blk = blockIdx.x;
    const int t = threadIdx.x;
    if (blk < 512) {
        // ---- bn_stats on x (C=64) ----
        constexpr int C = NI, G = 256 / C;
        __shared__ float sh[512];
        int c = t % C, g = t / C;
        float s = 0.f, s2 = 0.f;
        for (int r = blk * G + g; r < NN; r += 512 * G) {
            float v = x[(size_t)r * C + c];
            s += v; s2 += v * v;
        }
        sh[t] = s; sh[256 + t] = s2;
        __syncthreads();
        if (t < C) {
            float a = 0.f, b = 0.f;
            #pragma unroll
            for (int gg = 0; gg < G; ++gg) { a += sh[gg * C + t]; b += sh[256 + gg * C + t]; }
            part[blk * (2 * C) + t]     = a;
            part[blk * (2 * C) + C + t] = b;
        }
    } else if (blk < 904) {
        // ---- B fragment prep ----
        int b = blk - 512;
        int chunk = b >> 2, q = b & 3;
        const float* W; int CI, k, cc;
        if (chunk < 27)       { W = W1;  CI = 64;  k = chunk; cc = 0; }
        else if (chunk < 81)  { int c2 = chunk - 27; W = W2; CI = 128; k = c2 >> 1; cc = (c2 & 1) * 64; }
        else if (chunk == 81) { W = Wid; CI = 64;  k = 0; cc = 0; }
        else                  { int cd = chunk - 82; W = Wd; CI = 128; k = cd >> 1; cc = (cd & 1) * 64; }
        #pragma unroll
        for (int e = 0; e < 2; ++e) {
            int f = q * 512 + t * 2 + e;
            int warpN = f >> 9, kt = (f >> 7) & 3, half = (f >> 6) & 1;
            int lane = (f >> 1) & 31, nth = f & 1;
            int n  = warpN * 32 + (half * 2 + nth) * 8 + (lane >> 2);
            int ci = cc + kt * 16 + 2 * (lane & 3);
            const float* src = W + ((size_t)k * CI + ci) * 128 + n;
            unsigned h0 = __half_as_ushort(__float2half_rn(src[0]));
            unsigned h1 = __half_as_ushort(__float2half_rn(src[128]));
            unsigned h2 = __half_as_ushort(__float2half_rn(src[8 * 128]));
            unsigned h3 = __half_as_ushort(__float2half_rn(src[9 * 128]));
            uint2 v;
            v.x = h0 | (h1 << 16);
            v.y = h2 | (h3 << 16);
            PB[(size_t)chunk * 2048 + f] = v;
        }
    } else if (blk == 904) {
        // ---- time projection ----
        __shared__ float ts[BB * NE];
        for (int l = t; l < BB * NE; l += 256) ts[l] = silu_f(T[l]);
        __syncthreads();
        float acc[BB];
        #pragma unroll
        for (int b = 0; b < BB; ++b) acc[b] = 0.f;
        for (int e = 0; e < NE; ++e) {
            float w = Wt[e * 256 + t];
            #pragma unroll
            for (int b = 0; b < BB; ++b) acc[b] = fmaf(ts[b * NE + e], w, acc[b]);
        }
        float bias = bt[t];
        #pragma unroll
        for (int b = 0; b < BB; ++b) tp[b * 256 + t] = acc[b] + bias;
    } else {
        // ---- round x -> fp16 xr ----
        int i = (blk - 905) * 256 + t;
        int n8 = NN * NI / 8;
        if (i < n8) {
            const float4* X = (const float4*)x;
            float4 v0 = X[2 * i], v1 = X[2 * i + 1];
            union { uint4 u; __half2 h[4]; } o;
            o.h[0] = __floats2half2_rn(v0.x, v0.y);
            o.h[1] = __floats2half2_rn(v0.z, v0.w);
            o.h[2] = __floats2half2_rn(v1.x, v1.y);
            o.h[3] = __floats2half2_rn(v1.z, v1.w);
            xr[i] = o.u;
        }
    }
}

// ---------------- BN finalize (from stats blocks) ----------------
template<int C>
__global__ void bn_finalize_kernel(const float* __restrict__ part, int nblocks, float invn,
                                   const float* __restrict__ g, const float* __restrict__ be,
                                   float* __restrict__ mv) {
    constexpr int G = 512 / C;
    __shared__ float sh[1024];
    int t = threadIdx.x;
    int c = t % C, gg = t / C;
    float s = 0.f, s2 = 0.f;
    for (int b = gg; b < nblocks; b += G) {
        s  += part[b * 2 * C + c];
        s2 += part[b * 2 * C + C + c];
    }
    sh[t] = s; sh[512 + t] = s2;
    __syncthreads();
    if (t < C) {
        float a = 0.f, bsum = 0.f;
        #pragma unroll
        for (int q = 0; q < G; ++q) { a += sh[q * C + t]; bsum += sh[512 + q * C + t]; }
        float mean = a * invn;
        float var  = bsum * invn - mean * mean;
        float istd = rsqrtf(var + 1e-5f);
        float A = istd * g[t];
        mv[t]     = A;
        mv[C + t] = be[t] - mean * A;
    }
}

// ---------------- BN2 finalize from per-CTA conv1 partials ----------------
__global__ void bn_finalize_cpart_kernel(const float* __restrict__ cpart, float invn,
                                         const float* __restrict__ g, const float* __restrict__ be,
                                         float* __restrict__ mv) {
    __shared__ float sh[1024];
    __shared__ float tot[256];
    int t = threadIdx.x;             // 1024 threads
    int c = t & 255, gg = t >> 8;    // 4 groups
    float s = 0.f;
    for (int b = gg; b < NCTA; b += 4) s += cpart[(size_t)b * 256 + c];
    sh[t] = s;
    __syncthreads();
    if (t < 256) tot[t] = sh[t] + sh[256 + t] + sh[512 + t] + sh[768 + t];
    __syncthreads();
    if (t < 128) {
        float mean = tot[t] * invn;
        float var  = tot[128 + t] * invn - mean * mean;
        float istd = rsqrtf(var + 1e-5f);
        float A = istd * g[t];
        mv[t]       = A;
        mv[128 + t] = be[t] - mean * A;
    }
}

// ---------------- BN apply + SiLU -> fp16 ----------------
template<int C>
__global__ void bn_apply_silu_kernel(const float4* __restrict__ X, const float* __restrict__ mv,
                                     uint4* __restrict__ Y, int n8) {
    int i = blockIdx.x * 256 + threadIdx.x;
    if (i >= n8) return;
    int f = (i & (C / 8 - 1)) * 8;
    float4 v0 = X[2 * i], v1 = X[2 * i + 1];
    union { uint4 u; __half2 h[4]; } o;
    o.h[0] = __floats2half2_rn(silu_f(fmaf(v0.x, mv[f + 0], mv[C + f + 0])),
                               silu_f(fmaf(v0.y, mv[f + 1], mv[C + f + 1])));
    o.h[1] = __floats2half2_rn(silu_f(fmaf(v0.z, mv[f + 2], mv[C + f + 2])),
                               silu_f(fmaf(v0.w, mv[f + 3], mv[C + f + 3])));
    o.h[2] = __floats2half2_rn(silu_f(fmaf(v1.x, mv[f + 4], mv[C + f + 4])),
                               silu_f(fmaf(v1.y, mv[f + 5], mv[C + f + 5])));
    o.h[3] = __floats2half2_rn(silu_f(fmaf(v1.z, mv[f + 6], mv[C + f + 6])),
                               silu_f(fmaf(v1.w, mv[f + 7], mv[C + f + 7])));
    Y[i] = o.u;
}

// ---------------- fp16 mma.sync gather-GEMM, B direct from permuted gmem ----------------
// MODE: 0 = plain fp32 out, 1 = bias + FiLM fp32 out + per-CTA stats, 2 = bias+bias2 + idconv, fp16 out
template<int CIN, int MODE>
__global__ __launch_bounds__(256, 2)
void conv_mma_kernel(const __half* __restrict__ X, const int* __restrict__ nbr,
                     const uint4* __restrict__ PB, int chunk0,
                     const float* __restrict__ bias, const float* __restrict__ bias2,
                     const float* __restrict__ tp, const int* __restrict__ b_idx,
                     const __half* __restrict__ Xid, float* __restrict__ cpart,
                     void* __restrict__ outv, int M, int K) {
    extern __shared__ char sm[];
    const uint32_t smA = smem_u32(sm);            // A: 2 x 18432 B

    constexpr int CPK = CIN / 64;
    const int MAIN  = K * CPK;
    const int TOTAL = MAIN + ((MODE == 2) ? 1 : 0);
    const int nKC   = 4 * TOTAL;

    const int t = threadIdx.x;
    const int lane = t & 31, w = t >> 5;
    const int warpM = w >> 2, warpN = w & 3;
    const int rowBase = blockIdx.x * TILE_M;

    const int lr = t >> 1;
    const int lh = t & 1;

    const int aRow = warpM * 64 + (lane & 15);
    const int aSeg = lane >> 4;

    float acc[4][4][4];
    #pragma unroll
    for (int i = 0; i < 4; ++i)
        #pragma unroll
        for (int j = 0; j < 4; ++j)
            #pragma unroll
            for (int q = 0; q < 4; ++q) acc[i][j][q] = 0.f;

    // A-side chunk decode
    struct AChunk { const __half* a; int aCIN; const int* nb; int cc; };
    auto decode = [&](int c) -> AChunk {
        AChunk ch;
        if (MODE != 2 || c < MAIN) {
            int k  = c / CPK;
            ch.cc = (c - k * CPK) * 64;
            ch.a = X; ch.aCIN = CIN;
            ch.nb = nbr + (size_t)k * M;
        } else {
            ch.a = Xid; ch.aCIN = 64; ch.cc = 0;
            ch.nb = nullptr;
        }
        return ch;
    };

    uint4 va[4];
    auto ldA = [&](const AChunk& ch) {
        int row = rowBase + lr;
        int idx = -1;
        if (row < M) idx = ch.nb ? ch.nb[row] : row;
        if (idx >= 0) {
            const uint4* p = (const uint4*)(ch.a + (size_t)idx * ch.aCIN + ch.cc) + lh * 4;
            va[0] = p[0]; va[1] = p[1]; va[2] = p[2]; va[3] = p[3];
        } else {
            va[0] = va[1] = va[2] = va[3] = make_uint4(0, 0, 0, 0);
        }
    };
    auto stsA = [&](int bu) {
        char* dst = sm + bu * STAGE_BYTES + (lr * ROWU + lh * 4) * 16;
        #pragma unroll
        for (int j = 0; j < 4; ++j) ((uint4*)dst)[j] = va[j];
    };

    // B fragment prefetch (depth 2 over kt sequence)
    uint4 blo[2], bhi[2];
    const uint4* PBw = PB + warpN * 256 + lane;   // 4096B/256B in uint4 units
    #define ISSUE_B(kc, p) do {                                                  \
        const uint4* _q = PBw + (size_t)(chunk0 + ((kc) >> 2)) * 1024 + ((kc) & 3) * 64; \
        blo[p] = __ldg(_q);                                                      \
        bhi[p] = __ldg(_q + 32);                                                 \
    } while (0)

    ISSUE_B(0, 0);
    ISSUE_B(1, 1);

    // prologue A
    ldA(decode(0));

    for (int c = 0; c < TOTAL; ++c) {
        const int bu = c & 1;
        stsA(bu);
        __syncthreads();
        if (c + 1 < TOTAL) ldA(decode(c + 1));

        const uint32_t abuf = smA + bu * STAGE_BYTES;
        #pragma unroll
        for (int kt = 0; kt < 4; ++kt) {
            const int p = kt & 1;
            uint4 lo = blo[p], hi = bhi[p];
            int kc = c * 4 + kt;
            if (kc + 2 < nKC) ISSUE_B(kc + 2, p);
            uint32_t a[4][4];
            #pragma unroll
            for (int mt = 0; mt < 4; ++mt)
                ldsm4(a[mt], abuf + ((aRow + mt * 16) * ROWU + 2 * kt + aSeg) * 16);
            #pragma unroll
            for (int mt = 0; mt < 4; ++mt) {
                mma_f16(acc[mt][0], a[mt], lo.x, lo.y);
                mma_f16(acc[mt][1], a[mt], lo.z, lo.w);
                mma_f16(acc[mt][2], a[mt], hi.x, hi.y);
                mma_f16(acc[mt][3], a[mt], hi.z, hi.w);
            }
        }
    }
    #undef ISSUE_B

    // ---- epilogue ----
    float ss[8], sq[8];
    if (MODE == 1) {
        #pragma unroll
        for (int q = 0; q < 8; ++q) { ss[q] = 0.f; sq[q] = 0.f; }
    }
    #pragma unroll
    for (int mt = 0; mt < 4; ++mt) {
        int row0 = rowBase + warpM * 64 + mt * 16 + (lane >> 2);
        #pragma unroll
        for (int hr = 0; hr < 2; ++hr) {
            int row = row0 + 8 * hr;
            if (row >= M) continue;
            const float* tpr = (MODE == 1) ? (tp + b_idx[row] * 256) : nullptr;
            #pragma unroll
            for (int nt = 0; nt < 4; ++nt) {
                int col = warpN * 32 + nt * 8 + 2 * (lane & 3);
                float v0 = acc[mt][nt][2 * hr + 0];
                float v1 = acc[mt][nt][2 * hr + 1];
                if (MODE == 1) {
                    v0 = (v0 + bias[col])     * (1.f + tpr[col])     + tpr[128 + col];
                    v1 = (v1 + bias[col + 1]) * (1.f + tpr[col + 1]) + tpr[129 + col];
                    ss[2 * nt]     += v0; sq[2 * nt]     += v0 * v0;
                    ss[2 * nt + 1] += v1; sq[2 * nt + 1] += v1 * v1;
                    float* out = (float*)outv;
                    *(float2*)(out + (size_t)row * 128 + col) = make_float2(v0, v1);
                } else if (MODE == 2) {
                    v0 += bias[col] + bias2[col];
                    v1 += bias[col + 1] + bias2[col + 1];
                    __half* out = (__half*)outv;
                    *(__half2*)(out + (size_t)row * 128 + col) = __floats2half2_rn(v0, v1);
                } else {
                    float* out = (float*)outv;
                    *(float2*)(out + (size_t)row * 128 + col) = make_float2(v0, v1);
                }
            }
        }
    }

    if (MODE == 1) {
        #pragma unroll
        for (int q = 0; q < 8; ++q) {
            #pragma unroll
            for (int off = 4; off <= 16; off <<= 1) {
                ss[q] += __shfl_xor_sync(0xffffffff, ss[q], off);
                sq[q] += __shfl_xor_sync(0xffffffff, sq[q], off);
            }
        }
        __syncthreads();
        float* sstat = (float*)sm;       // [2 warpM][256]
        if (lane < 4) {
            #pragma unroll
            for (int nt = 0; nt < 4; ++nt)
                #pragma unroll
                for (int p = 0; p < 2; ++p) {
                    int col = warpN * 32 + nt * 8 + 2 * lane + p;
                    sstat[warpM * 256 + col]       = ss[2 * nt + p];
                    sstat[warpM * 256 + 128 + col] = sq[2 * nt + p];
                }
        }
        __syncthreads();
        if (t < 256)
            cpart[(size_t)blockIdx.x * 256 + t] = sstat[t] + sstat[256 + t];
    }
}

// ---------------- launch ----------------
extern "C" void kernel_launch(void* const* d_in, const int* in_sizes, int n_in,
                              void* d_out, int out_size) {
    const float* x     = (const float*)d_in[0];
    const float* t     = (const float*)d_in[1];
    const int*   b_idx = (const int*)  d_in[2];
    const int*   nbr   = (const int*)  d_in[3];
    const int*   nbrd  = (const int*)  d_in[4];
    const float* g1    = (const float*)d_in[5];
    const float* be1   = (const float*)d_in[6];
    const float* W1    = (const float*)d_in[7];
    const float* b1    = (const float*)d_in[8];
    const float* Wt    = (const float*)d_in[9];
    const float* bt    = (const float*)d_in[10];
    const float* g2    = (const float*)d_in[11];
    const float* be2   = (const float*)d_in[12];
    const float* W2    = (const float*)d_in[13];
    const float* b2    = (const float*)d_in[14];
    const float* Wid   = (const float*)d_in[15];
    const float* bid   = (const float*)d_in[16];
    const float* Wd    = (const float*)d_in[17];
    float* out = (float*)d_out;

    __half *pa, *ph2, *pxr;
    float *ph, *ppart, *pcpart, *pmv, *ptp;
    uint2 *pPB;
    cudaGetSymbolAddress((void**)&pa,     g_a);
    cudaGetSymbolAddress((void**)&ph,     g_h);
    cudaGetSymbolAddress((void**)&ph2,    g_h2);
    cudaGetSymbolAddress((void**)&pxr,    g_xr);
    cudaGetSymbolAddress((void**)&ppart,  g_part);
    cudaGetSymbolAddress((void**)&pcpart, g_cpart);
    cudaGetSymbolAddress((void**)&pmv,    g_mv);
    cudaGetSymbolAddress((void**)&ptp,    g_tp);
    cudaGetSymbolAddress((void**)&pPB,    g_PB);

    cudaFuncSetAttribute(conv_mma_kernel<64, 1>,  cudaFuncAttributeMaxDynamicSharedMemorySize, CONV_SMEM);
    cudaFuncSetAttribute(conv_mma_kernel<128, 2>, cudaFuncAttributeMaxDynamicSharedMemorySize, CONV_SMEM);
    cudaFuncSetAttribute(conv_mma_kernel<128, 0>, cudaFuncAttributeMaxDynamicSharedMemorySize, CONV_SMEM);

    const float invn = 1.0f / (float)NN;
    const int downGrid = (NDD + TILE_M - 1) / TILE_M;  // 196

    // launch 0: fused prologue (stats1 | B-frag prep | tproj | round x)
    prologue_kernel<<<905 + 6250, 256>>>(x, t, Wt, bt, W1, W2, Wid, Wd,
                                         ppart, ptp, pPB, (uint4*)pxr);
    // launch 1: BN1 finalize
    bn_finalize_kernel<NI><<<1, 512>>>(ppart, STATS_BLOCKS, invn, g1, be1, pmv);
    // launch 2: BN1 apply + SiLU -> a (fp16)
    {
        int n8 = NN * NI / 8;
        bn_apply_silu_kernel<NI><<<(n8 + 255) / 256, 256>>>((const float4*)x, pmv, (uint4*)pa, n8);
    }
    // launch 3 (ncu-profiled): conv1 (+bias +FiLM + stats) -> h (fp32)
    conv_mma_kernel<64, 1><<<NCTA, 256, CONV_SMEM>>>(
        pa, nbr, (const uint4*)pPB, 0, b1, nullptr, ptp, b_idx, nullptr, pcpart, ph, NN, KK);
    // launch 4: BN2 finalize from conv1 partials
    bn_finalize_cpart_kernel<<<1, 1024>>>(pcpart, invn, g2, be2, pmv);
    // launch 5: BN2 apply + SiLU -> a (fp16)
    {
        int n8 = NN * NFD / 8;
        bn_apply_silu_kernel<NFD><<<(n8 + 255) / 256, 256>>>((const float4*)ph, pmv, (uint4*)pa, n8);
    }
    // launch 6: conv2 + fused idconv (+b2+bid) -> h2 (fp16)
    conv_mma_kernel<128, 2><<<NCTA, 256, CONV_SMEM>>>(
        pa, nbr, (const uint4*)pPB, 27, b2, bid, nullptr, nullptr, pxr, nullptr, ph2, NN, KK);
    // launch 7: strided down conv -> out (fp32)
    conv_mma_kernel<128, 0><<<downGrid, 256, CONV_SMEM>>>(
        ph2, nbrd, (const uint4*)pPB, 82, nullptr, nullptr, nullptr, nullptr, nullptr, nullptr,
        out, NDD, KDD);

    (void)in_sizes; (void)n_in; (void)out_size;
}